// round 7
// baseline (speedup 1.0000x reference)
#include <cuda_runtime.h>
#include <cuda_fp16.h>
#include <math.h>

#define NU 100000
#define NI 50000
#define DD 64
#define EPSV 1e-12f
#define MAXH 3200000
#define MAXI 3000000

typedef long long ll;

static constexpr ll S  = (ll)NU * DD;
static constexpr ll SI = (ll)NI * DD;

// fp32 scratch: 4 accumulators
static constexpr ll ACC0 = 0;
static constexpr ll ACC1 = 1 * S;
static constexpr ll ACC2 = 2 * S;
static constexpr ll ACCS = 3 * S;
static constexpr ll TOT32 = 4 * S;
__device__ float g_buf[TOT32];

// fp16 gather-format scratch
static constexpr ll XG0 = 0;
static constexpr ll XG1 = 1 * S;
static constexpr ll XG2 = 2 * S;
static constexpr ll XGS = 3 * S;
static constexpr ll XT0 = 4 * S;
static constexpr ll XT1 = 5 * S;
static constexpr ll XT2 = 6 * S;
static constexpr ll XUS = 7 * S;
static constexpr ll XMIX = 8 * S;
static constexpr ll XIT  = 9 * S;
static constexpr ll XITA = 9 * S + SI;
static constexpr ll TOT16 = 9 * S + 2 * SI;
__device__ __half g_h[TOT16];

// CSR scratch
static constexpr int OFFLEN = 4 * (NU + 1) + (NI + 1);
__device__ int  g_off[OFFLEN];
__device__ int  g_cnt[OFFLEN];
__device__ int  g_rank[3 * (ll)MAXH + 2 * (ll)MAXI];
__device__ int2 g_pair[3 * (ll)MAXH + 2 * (ll)MAXI];

struct Spmm5 { const int* off[5]; const int2* pair[5];
               const __half* x[5]; __half* y[5]; float* acc[5]; };

// ---------------------------------------------------------------------------
__device__ __forceinline__ float warp_sum(float v) {
#pragma unroll
    for (int o = 16; o > 0; o >>= 1) v += __shfl_xor_sync(0xFFFFFFFFu, v, o);
    return v;
}

// compute v[lane*2 .. lane*2+1] redundantly per warp: v = att_mat @ att_agg
__device__ __forceinline__ float2 attn_v(const float* __restrict__ att_mat,
                                         const float* __restrict__ att_agg, int lane) {
    int d0 = lane * 2, d1 = lane * 2 + 1;
    float vx = 0.f, vy = 0.f;
#pragma unroll
    for (int j = 0; j < DD; ++j) {
        float ag = __ldg(att_agg + j);
        vx = fmaf(__ldg(att_mat + d0 * DD + j), ag, vx);
        vy = fmaf(__ldg(att_mat + d1 * DD + j), ag, vy);
    }
    return make_float2(vx, vy);
}

// ---------------------------------------------------------------------------
__global__ void zero_int_kernel(int* p, int n) {
    int i = blockIdx.x * blockDim.x + threadIdx.x;
    if (i < n) p[i] = 0;
}

// per-matrix histogram, 4 edges/thread, stores per-edge rank
__global__ void hist_kernel(const int* __restrict__ row, int nnz,
                            int* __restrict__ cnt, int* __restrict__ rank) {
    int i = (blockIdx.x * blockDim.x + threadIdx.x) * 4;
    if (i + 3 < nnz) {
        int4 r = *(const int4*)(row + i);
        int k0 = atomicAdd(cnt + r.x, 1);
        int k1 = atomicAdd(cnt + r.y, 1);
        int k2 = atomicAdd(cnt + r.z, 1);
        int k3 = atomicAdd(cnt + r.w, 1);
        *(int4*)(rank + i) = make_int4(k0, k1, k2, k3);
    } else {
        for (int j = i; j < nnz; ++j) rank[j] = atomicAdd(cnt + __ldg(row + j), 1);
    }
}

// one block per region; chunked exclusive scan of counts -> off
__global__ void scan_kernel() {
    int region = blockIdx.x;
    int n = (region == 4) ? NI : NU;
    int base = region * (NU + 1);
    int* cnt = g_cnt + base;
    int* off = g_off + base;
    const int T = 1024;
    int t = threadIdx.x;
    int chunk = (n + T - 1) / T;
    int lo = t * chunk;
    int hi = lo + chunk; if (hi > n) hi = n;
    int sum = 0;
    for (int i = lo; i < hi; ++i) sum += cnt[i];

    __shared__ int ws[32];
    int lane = t & 31, wid = t >> 5;
    int x = sum;
#pragma unroll
    for (int o = 1; o < 32; o <<= 1) {
        int y = __shfl_up_sync(0xFFFFFFFFu, x, o);
        if (lane >= o) x += y;
    }
    if (lane == 31) ws[wid] = x;
    __syncthreads();
    if (t < 32) {
        int y = ws[t];
#pragma unroll
        for (int o = 1; o < 32; o <<= 1) {
            int z = __shfl_up_sync(0xFFFFFFFFu, y, o);
            if (t >= o) y += z;
        }
        ws[t] = y;
    }
    __syncthreads();
    int pre = x - sum + ((wid > 0) ? ws[wid - 1] : 0);
    if (t == T - 1) off[n] = pre + sum;
    int run = pre;
    for (int i = lo; i < hi; ++i) {
        int v = cnt[i];
        off[i] = run;
        run += v;
    }
}

// per-matrix scatter, 4 edges/thread, atomic-free via rank
__global__ void scatter_kernel(const int* __restrict__ row, const int* __restrict__ col,
                               const float* __restrict__ val, int nnz,
                               const int* __restrict__ rank, const int* __restrict__ off,
                               int2* __restrict__ pair) {
    int i = (blockIdx.x * blockDim.x + threadIdx.x) * 4;
    if (i + 3 < nnz) {
        int4 r = *(const int4*)(row + i);
        int4 c = *(const int4*)(col + i);
        float4 v = *(const float4*)(val + i);
        int4 k = *(const int4*)(rank + i);
        pair[__ldg(off + r.x) + k.x] = make_int2(c.x, __float_as_int(v.x));
        pair[__ldg(off + r.y) + k.y] = make_int2(c.y, __float_as_int(v.y));
        pair[__ldg(off + r.z) + k.z] = make_int2(c.z, __float_as_int(v.z));
        pair[__ldg(off + r.w) + k.w] = make_int2(c.w, __float_as_int(v.w));
    } else {
        for (int j = i; j < nnz; ++j) {
            pair[__ldg(off + __ldg(row + j)) + __ldg(rank + j)] =
                make_int2(__ldg(col + j), __float_as_int(__ldg(val + j)));
        }
    }
}

// Fused 5-region CSR SpMM: one warp per row, cooperative pair loading via shfl,
// fp16 gathers, fp32 accumulate, fused l2norm-acc.
__global__ void spmm5_kernel(Spmm5 a) {
    ll gw = ((ll)blockIdx.x * blockDim.x + threadIdx.x) >> 5;
    int lane = threadIdx.x & 31;
    int region, row;
    if (gw < NU)                { region = 0; row = (int)gw; }
    else if (gw < 2 * NU)       { region = 1; row = (int)(gw - NU); }
    else if (gw < 3 * NU)       { region = 2; row = (int)(gw - 2 * NU); }
    else if (gw < 3 * NU + NI)  { region = 3; row = (int)(gw - 3 * NU); }
    else if (gw < 4 * NU + NI)  { region = 4; row = (int)(gw - 3 * NU - NI); }
    else return;

    const int* off = a.off[region];
    const int2* __restrict__ pair = a.pair[region];
    const __half* __restrict__ x16 = a.x[region];
    int s = __ldg(off + row), e = __ldg(off + row + 1);
    float ax = 0.f, ay = 0.f;
    int base = s;
    while (e - base >= 32) {
        int2 myp = __ldg(pair + base + lane);
#pragma unroll 8
        for (int j = 0; j < 32; ++j) {
            int c = __shfl_sync(0xFFFFFFFFu, myp.x, j);
            float v = __int_as_float(__shfl_sync(0xFFFFFFFFu, myp.y, j));
            float2 f = __half22float2(__ldg((const __half2*)(x16 + (ll)c * DD) + lane));
            ax = fmaf(v, f.x, ax); ay = fmaf(v, f.y, ay);
        }
        base += 32;
    }
    int rem = e - base;
    if (rem > 0) {
        int2 myp = (lane < rem) ? __ldg(pair + base + lane) : make_int2(0, 0);
        for (int j = 0; j < rem; ++j) {
            int c = __shfl_sync(0xFFFFFFFFu, myp.x, j);
            float v = __int_as_float(__shfl_sync(0xFFFFFFFFu, myp.y, j));
            float2 f = __half22float2(__ldg((const __half2*)(x16 + (ll)c * DD) + lane));
            ax = fmaf(v, f.x, ax); ay = fmaf(v, f.y, ay);
        }
    }

    __half* y16 = a.y[region];
    if (y16) ((__half2*)(y16 + (ll)row * DD))[lane] = __floats2half2_rn(ax, ay);
    float ss = warp_sum(ax * ax + ay * ay);
    float sc = 1.f / fmaxf(sqrtf(ss), EPSV);
    float* acc = a.acc[region];
    ll b2 = (ll)row * DD + lane * 2;
    float2 av = *(const float2*)(acc + b2);
    av.x = fmaf(ax, sc, av.x);
    av.y = fmaf(ay, sc, av.y);
    *(float2*)(acc + b2) = av;
}

__global__ void item_h_kernel(const float* __restrict__ src, __half* __restrict__ dst, int n2) {
    int i = blockIdx.x * blockDim.x + threadIdx.x;
    if (i < n2) {
        float2 v = ((const float2*)src)[i];
        ((__half2*)dst)[i] = __floats2half2_rn(v.x, v.y);
    }
}

// attention over fp16 inputs -> fp16 mixed; v computed in-warp
__global__ void attn_h_kernel(const __half* __restrict__ c0p, const __half* __restrict__ c1p,
                              const __half* __restrict__ c2p, const __half* __restrict__ othp,
                              const float* __restrict__ att_mat, const float* __restrict__ att_agg,
                              __half* __restrict__ out, int n_rows) {
    int w = (int)(((ll)blockIdx.x * blockDim.x + threadIdx.x) >> 5);
    if (w >= n_rows) return;
    int lane = threadIdx.x & 31;
    float2 vv = attn_v(att_mat, att_agg, lane);
    ll rb = (ll)w * DD;
    float2 c0 = __half22float2(((const __half2*)(c0p + rb))[lane]);
    float2 c1 = __half22float2(((const __half2*)(c1p + rb))[lane]);
    float2 c2 = __half22float2(((const __half2*)(c2p + rb))[lane]);
    float2 ot = __half22float2(((const __half2*)(othp + rb))[lane]);
    float w0 = warp_sum(c0.x * vv.x + c0.y * vv.y);
    float w1 = warp_sum(c1.x * vv.x + c1.y * vv.y);
    float w2 = warp_sum(c2.x * vv.x + c2.y * vv.y);
    float m = fmaxf(w0, fmaxf(w1, w2));
    float e0 = __expf(w0 - m), e1 = __expf(w1 - m), e2 = __expf(w2 - m);
    float inv = 1.f / (e0 + e1 + e2);
    float s0 = e0 * inv, s1 = e1 * inv, s2 = e2 * inv;
    float ox = 0.5f * (s0 * c0.x + s1 * c1.x + s2 * c2.x) + 0.5f * ot.x;
    float oy = 0.5f * (s0 * c0.y + s1 * c1.y + s2 * c2.y) + 0.5f * ot.y;
    ((__half2*)(out + rb))[lane] = __floats2half2_rn(ox, oy);
}

// final attention over fp32 accumulators -> fp32 out; v computed in-warp
__global__ void attn_f_kernel(const float* __restrict__ c0p, const float* __restrict__ c1p,
                              const float* __restrict__ c2p, const float* __restrict__ othp,
                              const float* __restrict__ att_mat, const float* __restrict__ att_agg,
                              float* __restrict__ out, int n_rows) {
    int w = (int)(((ll)blockIdx.x * blockDim.x + threadIdx.x) >> 5);
    if (w >= n_rows) return;
    int lane = threadIdx.x & 31;
    float2 vv = attn_v(att_mat, att_agg, lane);
    ll base = (ll)w * DD + lane * 2;
    float2 c0 = *(const float2*)(c0p + base);
    float2 c1 = *(const float2*)(c1p + base);
    float2 c2 = *(const float2*)(c2p + base);
    float2 ot = *(const float2*)(othp + base);
    float w0 = warp_sum(c0.x * vv.x + c0.y * vv.y);
    float w1 = warp_sum(c1.x * vv.x + c1.y * vv.y);
    float w2 = warp_sum(c2.x * vv.x + c2.y * vv.y);
    float m = fmaxf(w0, fmaxf(w1, w2));
    float e0 = __expf(w0 - m), e1 = __expf(w1 - m), e2 = __expf(w2 - m);
    float inv = 1.f / (e0 + e1 + e2);
    float s0 = e0 * inv, s1 = e1 * inv, s2 = e2 * inv;
    float ox = (s0 * c0.x + s1 * c1.x + s2 * c2.x) + 0.5f * ot.x;
    float oy = (s0 * c0.y + s1 * c1.y + s2 * c2.y) + 0.5f * ot.y;
    *(float2*)(out + base) = make_float2(ox, oy);
}

// self-gating, float4 LDS inner loop
__global__ void gating_kernel(const float* __restrict__ in, const float* __restrict__ W,
                              const float* __restrict__ B, int n_rows, int n_gates,
                              float* o0, float* o1, float* o2, float* o3,
                              __half* h0, __half* h1, __half* h2, __half* h3) {
    __shared__ float sW[DD * DD];
    __shared__ float se[32 * DD];
    int tx = threadIdx.x, ty = threadIdx.y;
    int tid = ty * 64 + tx;
    int row0 = blockIdx.x * 32;
    for (int i = tid; i < 32 * DD; i += 256) {
        int r = i >> 6, c = i & 63;
        int gr = row0 + r;
        se[i] = (gr < n_rows) ? in[(ll)gr * DD + c] : 0.f;
    }
    float* outs[4] = {o0, o1, o2, o3};
    __half* houts[4] = {h0, h1, h2, h3};
    for (int g = 0; g < n_gates; ++g) {
        __syncthreads();
        for (int i = tid; i < DD * DD; i += 256) sW[i] = W[(ll)g * DD * DD + i];
        __syncthreads();
        float bg = B[g * DD + tx];
        float acc[8] = {0, 0, 0, 0, 0, 0, 0, 0};
#pragma unroll
        for (int d4 = 0; d4 < DD; d4 += 4) {
            float w0 = sW[(d4 + 0) * DD + tx];
            float w1 = sW[(d4 + 1) * DD + tx];
            float w2 = sW[(d4 + 2) * DD + tx];
            float w3 = sW[(d4 + 3) * DD + tx];
#pragma unroll
            for (int rr = 0; rr < 8; ++rr) {
                float4 s4 = *(const float4*)(se + (ty + 4 * rr) * DD + d4);
                acc[rr] = fmaf(s4.x, w0, acc[rr]);
                acc[rr] = fmaf(s4.y, w1, acc[rr]);
                acc[rr] = fmaf(s4.z, w2, acc[rr]);
                acc[rr] = fmaf(s4.w, w3, acc[rr]);
            }
        }
#pragma unroll
        for (int rr = 0; rr < 8; ++rr) {
            int r = ty + 4 * rr;
            int gr = row0 + r;
            if (gr < n_rows) {
                float z = acc[rr] + bg;
                float sig = 1.f / (1.f + __expf(-z));
                float ov = se[r * DD + tx] * sig;
                ll idx = (ll)gr * DD + tx;
                if (outs[g]) outs[g][idx] = ov;
                if (houts[g]) houts[g][idx] = __float2half(ov);
            }
        }
    }
}

// ---------------------------------------------------------------------------
static inline int blocks_for(ll threads, int bs) { return (int)((threads + bs - 1) / bs); }

extern "C" void kernel_launch(void* const* d_in, const int* in_sizes, int n_in,
                              void* d_out, int out_size) {
    const float* user_emb  = (const float*)d_in[0];
    const float* item_emb  = (const float*)d_in[1];
    const float* gating_w  = (const float*)d_in[2];
    const float* gating_b  = (const float*)d_in[3];
    const float* sgating_w = (const float*)d_in[4];
    const float* sgating_b = (const float*)d_in[5];
    const float* att_mat   = (const float*)d_in[6];
    const float* att_agg   = (const float*)d_in[7];
    const int*   hs_row = (const int*)d_in[8];
    const int*   hs_col = (const int*)d_in[9];
    const float* hs_val = (const float*)d_in[10];
    const int*   hj_row = (const int*)d_in[11];
    const int*   hj_col = (const int*)d_in[12];
    const float* hj_val = (const float*)d_in[13];
    const int*   hp_row = (const int*)d_in[14];
    const int*   hp_col = (const int*)d_in[15];
    const float* hp_val = (const float*)d_in[16];
    const int*   inter_row = (const int*)d_in[17];
    const int*   inter_col = (const int*)d_in[18];
    const float* inter_val = (const float*)d_in[19];

    const int NNZ_H = in_sizes[8];
    const int NNZ_I = in_sizes[17];

    float* out = (float*)d_out;
    const ll O_ITEM = S;
    const ll O_SG0 = S + SI;
    const ll O_SG1 = 2 * S + SI;
    const ll O_SG2 = 3 * S + SI;

    float*  gb; cudaGetSymbolAddress((void**)&gb, g_buf);
    __half* gh; cudaGetSymbolAddress((void**)&gh, g_h);
    int*   off; cudaGetSymbolAddress((void**)&off, g_off);
    int*   cnt; cudaGetSymbolAddress((void**)&cnt, g_cnt);
    int*   rk;  cudaGetSymbolAddress((void**)&rk, g_rank);
    int2*  pr;  cudaGetSymbolAddress((void**)&pr, g_pair);

    const int BS = 256;
    dim3 gdim(64, 4);

    // region bases
    int* c0 = cnt + 0 * (NU + 1); int* f0 = off + 0 * (NU + 1);
    int* c1 = cnt + 1 * (NU + 1); int* f1 = off + 1 * (NU + 1);
    int* c2 = cnt + 2 * (NU + 1); int* f2 = off + 2 * (NU + 1);
    int* c3 = cnt + 3 * (NU + 1); int* f3 = off + 3 * (NU + 1);
    int* c4 = cnt + 4 * (NU + 1); int* f4 = off + 4 * (NU + 1);
    int2* p0 = pr;                 int* r0 = rk;
    int2* p1 = pr + (ll)NNZ_H;     int* r1 = rk + (ll)NNZ_H;
    int2* p2 = pr + 2ll * NNZ_H;   int* r2 = rk + 2ll * NNZ_H;
    int2* p3 = pr + 3ll * NNZ_H;   int* r3 = rk + 3ll * NNZ_H;
    int2* p4 = pr + 3ll * NNZ_H + NNZ_I; int* r4 = rk + 3ll * NNZ_H + NNZ_I;

    item_h_kernel<<<blocks_for(SI / 2, BS), BS>>>(item_emb, gh + XIT, (int)(SI / 2));
    cudaMemcpyAsync(out + O_ITEM, item_emb, SI * sizeof(float), cudaMemcpyDeviceToDevice, 0);

    // ---- CSR build ----
    zero_int_kernel<<<blocks_for(OFFLEN, BS), BS>>>(cnt, OFFLEN);
    const int hbH = blocks_for((NNZ_H + 3) / 4, BS);
    const int hbI = blocks_for((NNZ_I + 3) / 4, BS);
    hist_kernel<<<hbH, BS>>>(hs_row, NNZ_H, c0, r0);
    hist_kernel<<<hbH, BS>>>(hj_row, NNZ_H, c1, r1);
    hist_kernel<<<hbH, BS>>>(hp_row, NNZ_H, c2, r2);
    hist_kernel<<<hbI, BS>>>(inter_row, NNZ_I, c3, r3);
    hist_kernel<<<hbI, BS>>>(inter_col, NNZ_I, c4, r4);
    scan_kernel<<<5, 1024>>>();
    scatter_kernel<<<hbH, BS>>>(hs_row, hs_col, hs_val, NNZ_H, r0, f0, p0);
    scatter_kernel<<<hbH, BS>>>(hj_row, hj_col, hj_val, NNZ_H, r1, f1, p1);
    scatter_kernel<<<hbH, BS>>>(hp_row, hp_col, hp_val, NNZ_H, r2, f2, p2);
    scatter_kernel<<<hbI, BS>>>(inter_row, inter_col, inter_val, NNZ_I, r3, f3, p3);
    scatter_kernel<<<hbI, BS>>>(inter_col, inter_row, inter_val, NNZ_I, r4, f4, p4);

    // prologue gating
    gating_kernel<<<(NU + 31) / 32, gdim>>>(user_emb, gating_w, gating_b, NU, 4,
                                            gb + ACC0, gb + ACC1, gb + ACC2, gb + ACCS,
                                            gh + XG0, gh + XG1, gh + XG2, gh + XGS);

    const int uwb = blocks_for((ll)NU * 32, BS);
    const ll TOTW = 4ll * NU + NI;
    const int swb = blocks_for(TOTW * 32, BS);

    // ---- layer 1 ----
    attn_h_kernel<<<uwb, BS>>>(gh + XG0, gh + XG1, gh + XG2, gh + XGS,
                               att_mat, att_agg, gh + XMIX, NU);
    Spmm5 A1;
    A1.off[0] = f0; A1.pair[0] = p0; A1.x[0] = gh + XG0; A1.y[0] = gh + XT0; A1.acc[0] = gb + ACC0;
    A1.off[1] = f1; A1.pair[1] = p1; A1.x[1] = gh + XG1; A1.y[1] = gh + XT1; A1.acc[1] = gb + ACC1;
    A1.off[2] = f2; A1.pair[2] = p2; A1.x[2] = gh + XG2; A1.y[2] = gh + XT2; A1.acc[2] = gb + ACC2;
    A1.off[3] = f4; A1.pair[3] = p4; A1.x[3] = gh + XMIX; A1.y[3] = gh + XITA; A1.acc[3] = out + O_ITEM;
    A1.off[4] = f3; A1.pair[4] = p3; A1.x[4] = gh + XIT; A1.y[4] = gh + XUS; A1.acc[4] = gb + ACCS;
    spmm5_kernel<<<swb, BS>>>(A1);

    // ---- layer 2 ----
    attn_h_kernel<<<uwb, BS>>>(gh + XT0, gh + XT1, gh + XT2, gh + XUS,
                               att_mat, att_agg, gh + XMIX, NU);
    Spmm5 A2;
    A2.off[0] = f0; A2.pair[0] = p0; A2.x[0] = gh + XT0; A2.y[0] = nullptr; A2.acc[0] = gb + ACC0;
    A2.off[1] = f1; A2.pair[1] = p1; A2.x[1] = gh + XT1; A2.y[1] = nullptr; A2.acc[1] = gb + ACC1;
    A2.off[2] = f2; A2.pair[2] = p2; A2.x[2] = gh + XT2; A2.y[2] = nullptr; A2.acc[2] = gb + ACC2;
    A2.off[3] = f4; A2.pair[3] = p4; A2.x[3] = gh + XMIX; A2.y[3] = nullptr; A2.acc[3] = out + O_ITEM;
    A2.off[4] = f3; A2.pair[4] = p3; A2.x[4] = gh + XITA; A2.y[4] = nullptr; A2.acc[4] = gb + ACCS;
    spmm5_kernel<<<swb, BS>>>(A2);

    // ---- final ----
    attn_f_kernel<<<uwb, BS>>>(gb + ACC0, gb + ACC1, gb + ACC2, gb + ACCS,
                               att_mat, att_agg, out, NU);
    gating_kernel<<<(NU + 31) / 32, gdim>>>(out, sgating_w, sgating_b, NU, 3,
                                            out + O_SG0, out + O_SG1, out + O_SG2, nullptr,
                                            nullptr, nullptr, nullptr, nullptr);
}

// round 8
// speedup vs baseline: 4.0379x; 4.0379x over previous
#include <cuda_runtime.h>
#include <cuda_fp16.h>
#include <math.h>

#define NU 100000
#define NI 50000
#define DD 64
#define EPSV 1e-12f
#define MAXH 3200000
#define MAXI 3000000

typedef long long ll;

static constexpr ll S  = (ll)NU * DD;
static constexpr ll SI = (ll)NI * DD;

// fp32 scratch: 4 accumulators + v vector
static constexpr ll ACC0 = 0;
static constexpr ll ACC1 = 1 * S;
static constexpr ll ACC2 = 2 * S;
static constexpr ll ACCS = 3 * S;
static constexpr ll VOFF = 4 * S;
static constexpr ll TOT32 = VOFF + 64;
__device__ float g_buf[TOT32];

// fp16 gather-format scratch
static constexpr ll XG0 = 0;
static constexpr ll XG1 = 1 * S;
static constexpr ll XG2 = 2 * S;
static constexpr ll XGS = 3 * S;
static constexpr ll XT0 = 4 * S;
static constexpr ll XT1 = 5 * S;
static constexpr ll XT2 = 6 * S;
static constexpr ll XUS = 7 * S;
static constexpr ll XMIX = 8 * S;
static constexpr ll XIT  = 9 * S;
static constexpr ll XITA = 9 * S + SI;
static constexpr ll TOT16 = 9 * S + 2 * SI;
__device__ __half g_h[TOT16];

// CSR scratch
static constexpr int OFFLEN = 4 * (NU + 1) + (NI + 1);
__device__ int  g_off[OFFLEN];
__device__ int  g_cnt[OFFLEN];
__device__ int  g_rank[3 * (ll)MAXH + 2 * (ll)MAXI];
__device__ int2 g_pair[3 * (ll)MAXH + 2 * (ll)MAXI];

struct Build5 {
    const int* row[5]; const int* col[5]; const float* val[5];
    int* rank[5]; int* cnt[5]; const int* off[5]; int2* pair[5]; int nnz[5];
};
struct Spmm5 { const int* off[5]; const int2* pair[5];
               const __half* x[5]; __half* y[5]; float* acc[5]; };

// ---------------------------------------------------------------------------
__device__ __forceinline__ float warp_sum(float v) {
#pragma unroll
    for (int o = 16; o > 0; o >>= 1) v += __shfl_xor_sync(0xFFFFFFFFu, v, o);
    return v;
}

// ---------------------------------------------------------------------------
__global__ void zero_int_kernel(int* p, int n) {
    int i = blockIdx.x * blockDim.x + threadIdx.x;
    if (i < n) p[i] = 0;
}

// fused 5-region histogram, 4 edges/thread, stores per-edge rank
__global__ void hist5_kernel(Build5 b, int bpr) {
    int region = blockIdx.x / bpr;
    int bb = blockIdx.x - region * bpr;
    int nnz = b.nnz[region];
    const int* __restrict__ row = b.row[region];
    int* __restrict__ rank = b.rank[region];
    int* cnt = b.cnt[region];
    int i = (bb * 256 + threadIdx.x) * 4;
    if (i + 3 < nnz) {
        int4 r = *(const int4*)(row + i);
        int k0 = atomicAdd(cnt + r.x, 1);
        int k1 = atomicAdd(cnt + r.y, 1);
        int k2 = atomicAdd(cnt + r.z, 1);
        int k3 = atomicAdd(cnt + r.w, 1);
        *(int4*)(rank + i) = make_int4(k0, k1, k2, k3);
    } else {
        for (int j = i; j < nnz; ++j) rank[j] = atomicAdd(cnt + __ldg(row + j), 1);
    }
}

// one block per region; chunked exclusive scan of counts -> off
__global__ void scan_kernel() {
    int region = blockIdx.x;
    int n = (region == 4) ? NI : NU;
    int base = region * (NU + 1);
    int* cnt = g_cnt + base;
    int* off = g_off + base;
    const int T = 1024;
    int t = threadIdx.x;
    int chunk = (n + T - 1) / T;
    int lo = t * chunk;
    int hi = lo + chunk; if (hi > n) hi = n;
    int sum = 0;
    for (int i = lo; i < hi; ++i) sum += cnt[i];

    __shared__ int ws[32];
    int lane = t & 31, wid = t >> 5;
    int x = sum;
#pragma unroll
    for (int o = 1; o < 32; o <<= 1) {
        int y = __shfl_up_sync(0xFFFFFFFFu, x, o);
        if (lane >= o) x += y;
    }
    if (lane == 31) ws[wid] = x;
    __syncthreads();
    if (t < 32) {
        int y = ws[t];
#pragma unroll
        for (int o = 1; o < 32; o <<= 1) {
            int z = __shfl_up_sync(0xFFFFFFFFu, y, o);
            if (t >= o) y += z;
        }
        ws[t] = y;
    }
    __syncthreads();
    int pre = x - sum + ((wid > 0) ? ws[wid - 1] : 0);
    if (t == T - 1) off[n] = pre + sum;
    int run = pre;
    for (int i = lo; i < hi; ++i) {
        int v = cnt[i];
        off[i] = run;
        run += v;
    }
}

// fused 5-region scatter, 4 edges/thread, atomic-free via rank
__global__ void scat5_kernel(Build5 b, int bpr) {
    int region = blockIdx.x / bpr;
    int bb = blockIdx.x - region * bpr;
    int nnz = b.nnz[region];
    const int* __restrict__ row = b.row[region];
    const int* __restrict__ col = b.col[region];
    const float* __restrict__ val = b.val[region];
    const int* __restrict__ rank = b.rank[region];
    const int* __restrict__ off = b.off[region];
    int2* __restrict__ pair = b.pair[region];
    int i = (bb * 256 + threadIdx.x) * 4;
    if (i + 3 < nnz) {
        int4 r = *(const int4*)(row + i);
        int4 c = *(const int4*)(col + i);
        float4 v = *(const float4*)(val + i);
        int4 k = *(const int4*)(rank + i);
        pair[__ldg(off + r.x) + k.x] = make_int2(c.x, __float_as_int(v.x));
        pair[__ldg(off + r.y) + k.y] = make_int2(c.y, __float_as_int(v.y));
        pair[__ldg(off + r.z) + k.z] = make_int2(c.z, __float_as_int(v.z));
        pair[__ldg(off + r.w) + k.w] = make_int2(c.w, __float_as_int(v.w));
    } else {
        for (int j = i; j < nnz; ++j) {
            pair[__ldg(off + __ldg(row + j)) + __ldg(rank + j)] =
                make_int2(__ldg(col + j), __float_as_int(__ldg(val + j)));
        }
    }
}

// Fused 5-region CSR SpMM: one warp per row, cooperative pair loading via shfl,
// fp16 gathers, fp32 accumulate, fused l2norm-acc.
__global__ void spmm5_kernel(Spmm5 a) {
    ll gw = ((ll)blockIdx.x * blockDim.x + threadIdx.x) >> 5;
    int lane = threadIdx.x & 31;
    int region, row;
    if (gw < NU)                { region = 0; row = (int)gw; }
    else if (gw < 2 * NU)       { region = 1; row = (int)(gw - NU); }
    else if (gw < 3 * NU)       { region = 2; row = (int)(gw - 2 * NU); }
    else if (gw < 3 * NU + NI)  { region = 3; row = (int)(gw - 3 * NU); }
    else if (gw < 4 * NU + NI)  { region = 4; row = (int)(gw - 3 * NU - NI); }
    else return;

    const int* off = a.off[region];
    const int2* __restrict__ pair = a.pair[region];
    const __half* __restrict__ x16 = a.x[region];
    int s = __ldg(off + row), e = __ldg(off + row + 1);
    float ax = 0.f, ay = 0.f;
    int base = s;
    while (e - base >= 32) {
        int2 myp = __ldg(pair + base + lane);
#pragma unroll 8
        for (int j = 0; j < 32; ++j) {
            int c = __shfl_sync(0xFFFFFFFFu, myp.x, j);
            float v = __int_as_float(__shfl_sync(0xFFFFFFFFu, myp.y, j));
            float2 f = __half22float2(__ldg((const __half2*)(x16 + (ll)c * DD) + lane));
            ax = fmaf(v, f.x, ax); ay = fmaf(v, f.y, ay);
        }
        base += 32;
    }
    int rem = e - base;
    if (rem > 0) {
        int2 myp = (lane < rem) ? __ldg(pair + base + lane) : make_int2(0, 0);
        for (int j = 0; j < rem; ++j) {
            int c = __shfl_sync(0xFFFFFFFFu, myp.x, j);
            float v = __int_as_float(__shfl_sync(0xFFFFFFFFu, myp.y, j));
            float2 f = __half22float2(__ldg((const __half2*)(x16 + (ll)c * DD) + lane));
            ax = fmaf(v, f.x, ax); ay = fmaf(v, f.y, ay);
        }
    }

    __half* y16 = a.y[region];
    if (y16) ((__half2*)(y16 + (ll)row * DD))[lane] = __floats2half2_rn(ax, ay);
    float ss = warp_sum(ax * ax + ay * ay);
    float sc = 1.f / fmaxf(sqrtf(ss), EPSV);
    float* acc = a.acc[region];
    ll b2 = (ll)row * DD + lane * 2;
    float2 av = *(const float2*)(acc + b2);
    av.x = fmaf(ax, sc, av.x);
    av.y = fmaf(ay, sc, av.y);
    *(float2*)(acc + b2) = av;
}

// v[d] = sum_j att_mat[d][j] * att_agg[j]  (one tiny launch; coalesced enough)
__global__ void compute_v_kernel(const float* __restrict__ att_mat,
                                 const float* __restrict__ att_agg) {
    int d = threadIdx.x;
    float s = 0.f;
#pragma unroll
    for (int j = 0; j < DD; ++j) s = fmaf(att_mat[d * DD + j], att_agg[j], s);
    g_buf[VOFF + d] = s;
}

__global__ void item_h_kernel(const float* __restrict__ src, __half* __restrict__ dst, int n2) {
    int i = blockIdx.x * blockDim.x + threadIdx.x;
    if (i < n2) {
        float2 v = ((const float2*)src)[i];
        ((__half2*)dst)[i] = __floats2half2_rn(v.x, v.y);
    }
}

// attention over fp16 inputs -> fp16 mixed (v precomputed in g_buf)
__global__ void attn_h_kernel(const __half* __restrict__ c0p, const __half* __restrict__ c1p,
                              const __half* __restrict__ c2p, const __half* __restrict__ othp,
                              const float* __restrict__ v,
                              __half* __restrict__ out, int n_rows) {
    int w = (int)(((ll)blockIdx.x * blockDim.x + threadIdx.x) >> 5);
    if (w >= n_rows) return;
    int lane = threadIdx.x & 31;
    ll rb = (ll)w * DD;
    float2 c0 = __half22float2(((const __half2*)(c0p + rb))[lane]);
    float2 c1 = __half22float2(((const __half2*)(c1p + rb))[lane]);
    float2 c2 = __half22float2(((const __half2*)(c2p + rb))[lane]);
    float2 ot = __half22float2(((const __half2*)(othp + rb))[lane]);
    float2 vv = *(const float2*)(v + lane * 2);
    float w0 = warp_sum(c0.x * vv.x + c0.y * vv.y);
    float w1 = warp_sum(c1.x * vv.x + c1.y * vv.y);
    float w2 = warp_sum(c2.x * vv.x + c2.y * vv.y);
    float m = fmaxf(w0, fmaxf(w1, w2));
    float e0 = __expf(w0 - m), e1 = __expf(w1 - m), e2 = __expf(w2 - m);
    float inv = 1.f / (e0 + e1 + e2);
    float s0 = e0 * inv, s1 = e1 * inv, s2 = e2 * inv;
    float ox = 0.5f * (s0 * c0.x + s1 * c1.x + s2 * c2.x) + 0.5f * ot.x;
    float oy = 0.5f * (s0 * c0.y + s1 * c1.y + s2 * c2.y) + 0.5f * ot.y;
    ((__half2*)(out + rb))[lane] = __floats2half2_rn(ox, oy);
}

// final attention over fp32 accumulators -> fp32 out
__global__ void attn_f_kernel(const float* __restrict__ c0p, const float* __restrict__ c1p,
                              const float* __restrict__ c2p, const float* __restrict__ othp,
                              const float* __restrict__ v,
                              float* __restrict__ out, int n_rows) {
    int w = (int)(((ll)blockIdx.x * blockDim.x + threadIdx.x) >> 5);
    if (w >= n_rows) return;
    int lane = threadIdx.x & 31;
    ll base = (ll)w * DD + lane * 2;
    float2 c0 = *(const float2*)(c0p + base);
    float2 c1 = *(const float2*)(c1p + base);
    float2 c2 = *(const float2*)(c2p + base);
    float2 ot = *(const float2*)(othp + base);
    float2 vv = *(const float2*)(v + lane * 2);
    float w0 = warp_sum(c0.x * vv.x + c0.y * vv.y);
    float w1 = warp_sum(c1.x * vv.x + c1.y * vv.y);
    float w2 = warp_sum(c2.x * vv.x + c2.y * vv.y);
    float m = fmaxf(w0, fmaxf(w1, w2));
    float e0 = __expf(w0 - m), e1 = __expf(w1 - m), e2 = __expf(w2 - m);
    float inv = 1.f / (e0 + e1 + e2);
    float s0 = e0 * inv, s1 = e1 * inv, s2 = e2 * inv;
    float ox = (s0 * c0.x + s1 * c1.x + s2 * c2.x) + 0.5f * ot.x;
    float oy = (s0 * c0.y + s1 * c1.y + s2 * c2.y) + 0.5f * ot.y;
    *(float2*)(out + base) = make_float2(ox, oy);
}

// self-gating, float4 LDS inner loop; ONE gate per block (blockIdx.y = gate)
__global__ void gating_kernel(const float* __restrict__ in, const float* __restrict__ W,
                              const float* __restrict__ B, int n_rows,
                              float* o0, float* o1, float* o2, float* o3,
                              __half* h0, __half* h1, __half* h2, __half* h3) {
    __shared__ float sW[DD * DD];
    __shared__ float se[32 * DD];
    int g = blockIdx.y;
    int tx = threadIdx.x, ty = threadIdx.y;
    int tid = ty * 64 + tx;
    int row0 = blockIdx.x * 32;
    for (int i = tid; i < 32 * DD; i += 256) {
        int r = i >> 6, c = i & 63;
        int gr = row0 + r;
        se[i] = (gr < n_rows) ? in[(ll)gr * DD + c] : 0.f;
    }
    for (int i = tid; i < DD * DD; i += 256) sW[i] = W[(ll)g * DD * DD + i];
    __syncthreads();

    float* outs[4] = {o0, o1, o2, o3};
    __half* houts[4] = {h0, h1, h2, h3};
    float* og = outs[g];
    __half* hg = houts[g];

    float bg = B[g * DD + tx];
    float acc[8] = {0, 0, 0, 0, 0, 0, 0, 0};
#pragma unroll
    for (int d4 = 0; d4 < DD; d4 += 4) {
        float w0 = sW[(d4 + 0) * DD + tx];
        float w1 = sW[(d4 + 1) * DD + tx];
        float w2 = sW[(d4 + 2) * DD + tx];
        float w3 = sW[(d4 + 3) * DD + tx];
#pragma unroll
        for (int rr = 0; rr < 8; ++rr) {
            float4 s4 = *(const float4*)(se + (ty + 4 * rr) * DD + d4);
            acc[rr] = fmaf(s4.x, w0, acc[rr]);
            acc[rr] = fmaf(s4.y, w1, acc[rr]);
            acc[rr] = fmaf(s4.z, w2, acc[rr]);
            acc[rr] = fmaf(s4.w, w3, acc[rr]);
        }
    }
#pragma unroll
    for (int rr = 0; rr < 8; ++rr) {
        int r = ty + 4 * rr;
        int gr = row0 + r;
        if (gr < n_rows) {
            float z = acc[rr] + bg;
            float sig = 1.f / (1.f + __expf(-z));
            float ov = se[r * DD + tx] * sig;
            ll idx = (ll)gr * DD + tx;
            if (og) og[idx] = ov;
            if (hg) hg[idx] = __float2half(ov);
        }
    }
}

// ---------------------------------------------------------------------------
static inline int blocks_for(ll threads, int bs) { return (int)((threads + bs - 1) / bs); }

extern "C" void kernel_launch(void* const* d_in, const int* in_sizes, int n_in,
                              void* d_out, int out_size) {
    const float* user_emb  = (const float*)d_in[0];
    const float* item_emb  = (const float*)d_in[1];
    const float* gating_w  = (const float*)d_in[2];
    const float* gating_b  = (const float*)d_in[3];
    const float* sgating_w = (const float*)d_in[4];
    const float* sgating_b = (const float*)d_in[5];
    const float* att_mat   = (const float*)d_in[6];
    const float* att_agg   = (const float*)d_in[7];
    const int*   hs_row = (const int*)d_in[8];
    const int*   hs_col = (const int*)d_in[9];
    const float* hs_val = (const float*)d_in[10];
    const int*   hj_row = (const int*)d_in[11];
    const int*   hj_col = (const int*)d_in[12];
    const float* hj_val = (const float*)d_in[13];
    const int*   hp_row = (const int*)d_in[14];
    const int*   hp_col = (const int*)d_in[15];
    const float* hp_val = (const float*)d_in[16];
    const int*   inter_row = (const int*)d_in[17];
    const int*   inter_col = (const int*)d_in[18];
    const float* inter_val = (const float*)d_in[19];

    const int NNZ_H = in_sizes[8];
    const int NNZ_I = in_sizes[17];

    float* out = (float*)d_out;
    const ll O_ITEM = S;
    const ll O_SG0 = S + SI;
    const ll O_SG1 = 2 * S + SI;
    const ll O_SG2 = 3 * S + SI;

    float*  gb; cudaGetSymbolAddress((void**)&gb, g_buf);
    __half* gh; cudaGetSymbolAddress((void**)&gh, g_h);
    int*   off; cudaGetSymbolAddress((void**)&off, g_off);
    int*   cnt; cudaGetSymbolAddress((void**)&cnt, g_cnt);
    int*   rk;  cudaGetSymbolAddress((void**)&rk, g_rank);
    int2*  pr;  cudaGetSymbolAddress((void**)&pr, g_pair);

    const int BS = 256;

    Build5 B;
    B.row[0] = hs_row;    B.col[0] = hs_col;    B.val[0] = hs_val;    B.nnz[0] = NNZ_H;
    B.row[1] = hj_row;    B.col[1] = hj_col;    B.val[1] = hj_val;    B.nnz[1] = NNZ_H;
    B.row[2] = hp_row;    B.col[2] = hp_col;    B.val[2] = hp_val;    B.nnz[2] = NNZ_H;
    B.row[3] = inter_row; B.col[3] = inter_col; B.val[3] = inter_val; B.nnz[3] = NNZ_I;
    B.row[4] = inter_col; B.col[4] = inter_row; B.val[4] = inter_val; B.nnz[4] = NNZ_I;
    ll po = 0, ro = 0;
    for (int m = 0; m < 5; ++m) {
        B.cnt[m] = cnt + m * (NU + 1);
        B.off[m] = off + m * (NU + 1);
        B.pair[m] = pr + po;  po += B.nnz[m];
        B.rank[m] = rk + ro;  ro += B.nnz[m];
    }

    compute_v_kernel<<<1, 64>>>(att_mat, att_agg);
    item_h_kernel<<<blocks_for(SI / 2, BS), BS>>>(item_emb, gh + XIT, (int)(SI / 2));
    cudaMemcpyAsync(out + O_ITEM, item_emb, SI * sizeof(float), cudaMemcpyDeviceToDevice, 0);

    // ---- CSR build (R6-proven fused shape) ----
    zero_int_kernel<<<blocks_for(OFFLEN, BS), BS>>>(cnt, OFFLEN);
    int bpr = blocks_for((NNZ_H + 3) / 4, BS);
    hist5_kernel<<<5 * bpr, BS>>>(B, bpr);
    scan_kernel<<<5, 1024>>>();
    scat5_kernel<<<5 * bpr, BS>>>(B, bpr);

    // prologue gating: 4 gates via gridDim.y
    dim3 gdim(64, 4);
    dim3 ggrid4((NU + 31) / 32, 4);
    gating_kernel<<<ggrid4, gdim>>>(user_emb, gating_w, gating_b, NU,
                                    gb + ACC0, gb + ACC1, gb + ACC2, gb + ACCS,
                                    gh + XG0, gh + XG1, gh + XG2, gh + XGS);

    const int uwb = blocks_for((ll)NU * 32, BS);
    const ll TOTW = 4ll * NU + NI;
    const int swb = blocks_for(TOTW * 32, BS);

    // ---- layer 1 ----
    attn_h_kernel<<<uwb, BS>>>(gh + XG0, gh + XG1, gh + XG2, gh + XGS, gb + VOFF,
                               gh + XMIX, NU);
    Spmm5 A1;
    A1.off[0] = B.off[0]; A1.pair[0] = B.pair[0]; A1.x[0] = gh + XG0; A1.y[0] = gh + XT0; A1.acc[0] = gb + ACC0;
    A1.off[1] = B.off[1]; A1.pair[1] = B.pair[1]; A1.x[1] = gh + XG1; A1.y[1] = gh + XT1; A1.acc[1] = gb + ACC1;
    A1.off[2] = B.off[2]; A1.pair[2] = B.pair[2]; A1.x[2] = gh + XG2; A1.y[2] = gh + XT2; A1.acc[2] = gb + ACC2;
    A1.off[3] = B.off[4]; A1.pair[3] = B.pair[4]; A1.x[3] = gh + XMIX; A1.y[3] = gh + XITA; A1.acc[3] = out + O_ITEM;
    A1.off[4] = B.off[3]; A1.pair[4] = B.pair[3]; A1.x[4] = gh + XIT; A1.y[4] = gh + XUS; A1.acc[4] = gb + ACCS;
    spmm5_kernel<<<swb, BS>>>(A1);

    // ---- layer 2 ----
    attn_h_kernel<<<uwb, BS>>>(gh + XT0, gh + XT1, gh + XT2, gh + XUS, gb + VOFF,
                               gh + XMIX, NU);
    Spmm5 A2;
    A2.off[0] = B.off[0]; A2.pair[0] = B.pair[0]; A2.x[0] = gh + XT0; A2.y[0] = nullptr; A2.acc[0] = gb + ACC0;
    A2.off[1] = B.off[1]; A2.pair[1] = B.pair[1]; A2.x[1] = gh + XT1; A2.y[1] = nullptr; A2.acc[1] = gb + ACC1;
    A2.off[2] = B.off[2]; A2.pair[2] = B.pair[2]; A2.x[2] = gh + XT2; A2.y[2] = nullptr; A2.acc[2] = gb + ACC2;
    A2.off[3] = B.off[4]; A2.pair[3] = B.pair[4]; A2.x[3] = gh + XMIX; A2.y[3] = nullptr; A2.acc[3] = out + O_ITEM;
    A2.off[4] = B.off[3]; A2.pair[4] = B.pair[3]; A2.x[4] = gh + XITA; A2.y[4] = nullptr; A2.acc[4] = gb + ACCS;
    spmm5_kernel<<<swb, BS>>>(A2);

    // ---- final ----
    attn_f_kernel<<<uwb, BS>>>(gb + ACC0, gb + ACC1, gb + ACC2, gb + ACCS, gb + VOFF,
                               out, NU);
    dim3 ggrid3((NU + 31) / 32, 3);
    gating_kernel<<<ggrid3, gdim>>>(out, sgating_w, sgating_b, NU,
                                    out + O_SG0, out + O_SG1, out + O_SG2, nullptr,
                                    nullptr, nullptr, nullptr, nullptr);
}

// round 9
// speedup vs baseline: 4.2894x; 1.0623x over previous
#include <cuda_runtime.h>
#include <cuda_fp16.h>
#include <math.h>

#define NU 100000
#define NI 50000
#define DD 64
#define EPSV 1e-12f
#define MAXH 3200000
#define MAXI 3000000

typedef long long ll;

static constexpr ll S  = (ll)NU * DD;
static constexpr ll SI = (ll)NI * DD;

// fp32 scratch: 4 accumulators + v vector
static constexpr ll ACC0 = 0;
static constexpr ll ACC1 = 1 * S;
static constexpr ll ACC2 = 2 * S;
static constexpr ll ACCS = 3 * S;
static constexpr ll VOFF = 4 * S;
static constexpr ll TOT32 = VOFF + 64;
__device__ float g_buf[TOT32];

// fp16 gather-format scratch
static constexpr ll XG0 = 0;
static constexpr ll XG1 = 1 * S;
static constexpr ll XG2 = 2 * S;
static constexpr ll XGS = 3 * S;
static constexpr ll XT0 = 4 * S;
static constexpr ll XT1 = 5 * S;
static constexpr ll XT2 = 6 * S;
static constexpr ll XUS = 7 * S;
static constexpr ll XMIX = 8 * S;
static constexpr ll XIT  = 9 * S;
static constexpr ll XITA = 9 * S + SI;
static constexpr ll TOT16 = 9 * S + 2 * SI;
__device__ __half g_h[TOT16];

// CSR scratch
static constexpr int OFFLEN = 4 * (NU + 1) + (NI + 1);
__device__ int  g_off[OFFLEN];
__device__ int  g_cnt[OFFLEN];
__device__ int  g_rank[3 * (ll)MAXH + 2 * (ll)MAXI];
__device__ int2 g_pair[3 * (ll)MAXH + 2 * (ll)MAXI];

struct Build5 {
    const int* row[5]; const int* col[5]; const float* val[5];
    int* rank[5]; int* cnt[5]; const int* off[5]; int2* pair[5]; int nnz[5];
};
struct Spmm5 { const int* off[5]; const int2* pair[5];
               const __half* x[5]; __half* y[5]; float* acc[5]; };

// ---------------------------------------------------------------------------
__device__ __forceinline__ float warp_sum(float v) {
#pragma unroll
    for (int o = 16; o > 0; o >>= 1) v += __shfl_xor_sync(0xFFFFFFFFu, v, o);
    return v;
}

// ---------------------------------------------------------------------------
__global__ void zero_int_kernel(int* p, int n) {
    int i = blockIdx.x * blockDim.x + threadIdx.x;
    if (i < n) p[i] = 0;
}

// fused 5-region histogram, 4 edges/thread, stores per-edge rank
__global__ void hist5_kernel(Build5 b, int bpr) {
    int region = blockIdx.x / bpr;
    int bb = blockIdx.x - region * bpr;
    int nnz = b.nnz[region];
    const int* __restrict__ row = b.row[region];
    int* __restrict__ rank = b.rank[region];
    int* cnt = b.cnt[region];
    int i = (bb * 256 + threadIdx.x) * 4;
    if (i + 3 < nnz) {
        int4 r = *(const int4*)(row + i);
        int k0 = atomicAdd(cnt + r.x, 1);
        int k1 = atomicAdd(cnt + r.y, 1);
        int k2 = atomicAdd(cnt + r.z, 1);
        int k3 = atomicAdd(cnt + r.w, 1);
        *(int4*)(rank + i) = make_int4(k0, k1, k2, k3);
    } else {
        for (int j = i; j < nnz; ++j) rank[j] = atomicAdd(cnt + __ldg(row + j), 1);
    }
}

// one block per region; chunked exclusive scan of counts -> off
__global__ void scan_kernel() {
    int region = blockIdx.x;
    int n = (region == 4) ? NI : NU;
    int base = region * (NU + 1);
    int* cnt = g_cnt + base;
    int* off = g_off + base;
    const int T = 1024;
    int t = threadIdx.x;
    int chunk = (n + T - 1) / T;
    int lo = t * chunk;
    int hi = lo + chunk; if (hi > n) hi = n;
    int sum = 0;
    for (int i = lo; i < hi; ++i) sum += cnt[i];

    __shared__ int ws[32];
    int lane = t & 31, wid = t >> 5;
    int x = sum;
#pragma unroll
    for (int o = 1; o < 32; o <<= 1) {
        int y = __shfl_up_sync(0xFFFFFFFFu, x, o);
        if (lane >= o) x += y;
    }
    if (lane == 31) ws[wid] = x;
    __syncthreads();
    if (t < 32) {
        int y = ws[t];
#pragma unroll
        for (int o = 1; o < 32; o <<= 1) {
            int z = __shfl_up_sync(0xFFFFFFFFu, y, o);
            if (t >= o) y += z;
        }
        ws[t] = y;
    }
    __syncthreads();
    int pre = x - sum + ((wid > 0) ? ws[wid - 1] : 0);
    if (t == T - 1) off[n] = pre + sum;
    int run = pre;
    for (int i = lo; i < hi; ++i) {
        int v = cnt[i];
        off[i] = run;
        run += v;
    }
}

// fused 5-region scatter, 4 edges/thread, atomic-free via rank
__global__ void scat5_kernel(Build5 b, int bpr) {
    int region = blockIdx.x / bpr;
    int bb = blockIdx.x - region * bpr;
    int nnz = b.nnz[region];
    const int* __restrict__ row = b.row[region];
    const int* __restrict__ col = b.col[region];
    const float* __restrict__ val = b.val[region];
    const int* __restrict__ rank = b.rank[region];
    const int* __restrict__ off = b.off[region];
    int2* __restrict__ pair = b.pair[region];
    int i = (bb * 256 + threadIdx.x) * 4;
    if (i + 3 < nnz) {
        int4 r = *(const int4*)(row + i);
        int4 c = *(const int4*)(col + i);
        float4 v = *(const float4*)(val + i);
        int4 k = *(const int4*)(rank + i);
        pair[__ldg(off + r.x) + k.x] = make_int2(c.x, __float_as_int(v.x));
        pair[__ldg(off + r.y) + k.y] = make_int2(c.y, __float_as_int(v.y));
        pair[__ldg(off + r.z) + k.z] = make_int2(c.z, __float_as_int(v.z));
        pair[__ldg(off + r.w) + k.w] = make_int2(c.w, __float_as_int(v.w));
    } else {
        for (int j = i; j < nnz; ++j) {
            pair[__ldg(off + __ldg(row + j)) + __ldg(rank + j)] =
                make_int2(__ldg(col + j), __float_as_int(__ldg(val + j)));
        }
    }
}

// Fused 5-region CSR SpMM: one warp per row, cooperative pair loading via shfl,
// fp16 gathers, fp32 accumulate, fused l2norm-acc.
__global__ void spmm5_kernel(Spmm5 a) {
    ll gw = ((ll)blockIdx.x * blockDim.x + threadIdx.x) >> 5;
    int lane = threadIdx.x & 31;
    int region, row;
    if (gw < NU)                { region = 0; row = (int)gw; }
    else if (gw < 2 * NU)       { region = 1; row = (int)(gw - NU); }
    else if (gw < 3 * NU)       { region = 2; row = (int)(gw - 2 * NU); }
    else if (gw < 3 * NU + NI)  { region = 3; row = (int)(gw - 3 * NU); }
    else if (gw < 4 * NU + NI)  { region = 4; row = (int)(gw - 3 * NU - NI); }
    else return;

    const int* off = a.off[region];
    const int2* __restrict__ pair = a.pair[region];
    const __half* __restrict__ x16 = a.x[region];
    int s = __ldg(off + row), e = __ldg(off + row + 1);
    float ax = 0.f, ay = 0.f;
    int base = s;
    while (e - base >= 32) {
        int2 myp = __ldg(pair + base + lane);
#pragma unroll 8
        for (int j = 0; j < 32; ++j) {
            int c = __shfl_sync(0xFFFFFFFFu, myp.x, j);
            float v = __int_as_float(__shfl_sync(0xFFFFFFFFu, myp.y, j));
            float2 f = __half22float2(__ldg((const __half2*)(x16 + (ll)c * DD) + lane));
            ax = fmaf(v, f.x, ax); ay = fmaf(v, f.y, ay);
        }
        base += 32;
    }
    int rem = e - base;
    if (rem > 0) {
        int2 myp = (lane < rem) ? __ldg(pair + base + lane) : make_int2(0, 0);
        for (int j = 0; j < rem; ++j) {
            int c = __shfl_sync(0xFFFFFFFFu, myp.x, j);
            float v = __int_as_float(__shfl_sync(0xFFFFFFFFu, myp.y, j));
            float2 f = __half22float2(__ldg((const __half2*)(x16 + (ll)c * DD) + lane));
            ax = fmaf(v, f.x, ax); ay = fmaf(v, f.y, ay);
        }
    }

    __half* y16 = a.y[region];
    if (y16) ((__half2*)(y16 + (ll)row * DD))[lane] = __floats2half2_rn(ax, ay);
    float ss = warp_sum(ax * ax + ay * ay);
    float sc = 1.f / fmaxf(sqrtf(ss), EPSV);
    float* acc = a.acc[region];
    ll b2 = (ll)row * DD + lane * 2;
    float2 av = *(const float2*)(acc + b2);
    av.x = fmaf(ax, sc, av.x);
    av.y = fmaf(ay, sc, av.y);
    *(float2*)(acc + b2) = av;
}

// v[d] = sum_j att_mat[d][j] * att_agg[j]
__global__ void compute_v_kernel(const float* __restrict__ att_mat,
                                 const float* __restrict__ att_agg) {
    int d = threadIdx.x;
    float s = 0.f;
#pragma unroll
    for (int j = 0; j < DD; ++j) s = fmaf(att_mat[d * DD + j], att_agg[j], s);
    g_buf[VOFF + d] = s;
}

__global__ void item_h_kernel(const float* __restrict__ src, __half* __restrict__ dst, int n2) {
    int i = blockIdx.x * blockDim.x + threadIdx.x;
    if (i < n2) {
        float2 v = ((const float2*)src)[i];
        ((__half2*)dst)[i] = __floats2half2_rn(v.x, v.y);
    }
}

// attention over fp16 inputs -> fp16 mixed (v precomputed in g_buf)
__global__ void attn_h_kernel(const __half* __restrict__ c0p, const __half* __restrict__ c1p,
                              const __half* __restrict__ c2p, const __half* __restrict__ othp,
                              const float* __restrict__ v,
                              __half* __restrict__ out, int n_rows) {
    int w = (int)(((ll)blockIdx.x * blockDim.x + threadIdx.x) >> 5);
    if (w >= n_rows) return;
    int lane = threadIdx.x & 31;
    ll rb = (ll)w * DD;
    float2 c0 = __half22float2(((const __half2*)(c0p + rb))[lane]);
    float2 c1 = __half22float2(((const __half2*)(c1p + rb))[lane]);
    float2 c2 = __half22float2(((const __half2*)(c2p + rb))[lane]);
    float2 ot = __half22float2(((const __half2*)(othp + rb))[lane]);
    float2 vv = *(const float2*)(v + lane * 2);
    float w0 = warp_sum(c0.x * vv.x + c0.y * vv.y);
    float w1 = warp_sum(c1.x * vv.x + c1.y * vv.y);
    float w2 = warp_sum(c2.x * vv.x + c2.y * vv.y);
    float m = fmaxf(w0, fmaxf(w1, w2));
    float e0 = __expf(w0 - m), e1 = __expf(w1 - m), e2 = __expf(w2 - m);
    float inv = 1.f / (e0 + e1 + e2);
    float s0 = e0 * inv, s1 = e1 * inv, s2 = e2 * inv;
    float ox = 0.5f * (s0 * c0.x + s1 * c1.x + s2 * c2.x) + 0.5f * ot.x;
    float oy = 0.5f * (s0 * c0.y + s1 * c1.y + s2 * c2.y) + 0.5f * ot.y;
    ((__half2*)(out + rb))[lane] = __floats2half2_rn(ox, oy);
}

// final attention over fp32 accumulators -> fp32 out
__global__ void attn_f_kernel(const float* __restrict__ c0p, const float* __restrict__ c1p,
                              const float* __restrict__ c2p, const float* __restrict__ othp,
                              const float* __restrict__ v,
                              float* __restrict__ out, int n_rows) {
    int w = (int)(((ll)blockIdx.x * blockDim.x + threadIdx.x) >> 5);
    if (w >= n_rows) return;
    int lane = threadIdx.x & 31;
    ll base = (ll)w * DD + lane * 2;
    float2 c0 = *(const float2*)(c0p + base);
    float2 c1 = *(const float2*)(c1p + base);
    float2 c2 = *(const float2*)(c2p + base);
    float2 ot = *(const float2*)(othp + base);
    float2 vv = *(const float2*)(v + lane * 2);
    float w0 = warp_sum(c0.x * vv.x + c0.y * vv.y);
    float w1 = warp_sum(c1.x * vv.x + c1.y * vv.y);
    float w2 = warp_sum(c2.x * vv.x + c2.y * vv.y);
    float m = fmaxf(w0, fmaxf(w1, w2));
    float e0 = __expf(w0 - m), e1 = __expf(w1 - m), e2 = __expf(w2 - m);
    float inv = 1.f / (e0 + e1 + e2);
    float s0 = e0 * inv, s1 = e1 * inv, s2 = e2 * inv;
    float ox = (s0 * c0.x + s1 * c1.x + s2 * c2.x) + 0.5f * ot.x;
    float oy = (s0 * c0.y + s1 * c1.y + s2 * c2.y) + 0.5f * ot.y;
    *(float2*)(out + base) = make_float2(ox, oy);
}

// self-gating, float4 LDS inner loop; ONE gate per block (blockIdx.y = gate)
__global__ void gating_kernel(const float* __restrict__ in, const float* __restrict__ W,
                              const float* __restrict__ B, int n_rows,
                              float* o0, float* o1, float* o2, float* o3,
                              __half* h0, __half* h1, __half* h2, __half* h3) {
    __shared__ float sW[DD * DD];
    __shared__ float se[32 * DD];
    int g = blockIdx.y;
    int tx = threadIdx.x, ty = threadIdx.y;
    int tid = ty * 64 + tx;
    int row0 = blockIdx.x * 32;
    for (int i = tid; i < 32 * DD; i += 256) {
        int r = i >> 6, c = i & 63;
        int gr = row0 + r;
        se[i] = (gr < n_rows) ? in[(ll)gr * DD + c] : 0.f;
    }
    for (int i = tid; i < DD * DD; i += 256) sW[i] = W[(ll)g * DD * DD + i];
    __syncthreads();

    float* outs[4] = {o0, o1, o2, o3};
    __half* houts[4] = {h0, h1, h2, h3};
    float* og = outs[g];
    __half* hg = houts[g];

    float bg = B[g * DD + tx];
    float acc[8] = {0, 0, 0, 0, 0, 0, 0, 0};
#pragma unroll
    for (int d4 = 0; d4 < DD; d4 += 4) {
        float w0 = sW[(d4 + 0) * DD + tx];
        float w1 = sW[(d4 + 1) * DD + tx];
        float w2 = sW[(d4 + 2) * DD + tx];
        float w3 = sW[(d4 + 3) * DD + tx];
#pragma unroll
        for (int rr = 0; rr < 8; ++rr) {
            float4 s4 = *(const float4*)(se + (ty + 4 * rr) * DD + d4);
            acc[rr] = fmaf(s4.x, w0, acc[rr]);
            acc[rr] = fmaf(s4.y, w1, acc[rr]);
            acc[rr] = fmaf(s4.z, w2, acc[rr]);
            acc[rr] = fmaf(s4.w, w3, acc[rr]);
        }
    }
#pragma unroll
    for (int rr = 0; rr < 8; ++rr) {
        int r = ty + 4 * rr;
        int gr = row0 + r;
        if (gr < n_rows) {
            float z = acc[rr] + bg;
            float sig = 1.f / (1.f + __expf(-z));
            float ov = se[r * DD + tx] * sig;
            ll idx = (ll)gr * DD + tx;
            if (og) og[idx] = ov;
            if (hg) hg[idx] = __float2half(ov);
        }
    }
}

// ---------------------------------------------------------------------------
static inline int blocks_for(ll threads, int bs) { return (int)((threads + bs - 1) / bs); }

extern "C" void kernel_launch(void* const* d_in, const int* in_sizes, int n_in,
                              void* d_out, int out_size) {
    const float* user_emb  = (const float*)d_in[0];
    const float* item_emb  = (const float*)d_in[1];
    const float* gating_w  = (const float*)d_in[2];
    const float* gating_b  = (const float*)d_in[3];
    const float* sgating_w = (const float*)d_in[4];
    const float* sgating_b = (const float*)d_in[5];
    const float* att_mat   = (const float*)d_in[6];
    const float* att_agg   = (const float*)d_in[7];
    const int*   hs_row = (const int*)d_in[8];
    const int*   hs_col = (const int*)d_in[9];
    const float* hs_val = (const float*)d_in[10];
    const int*   hj_row = (const int*)d_in[11];
    const int*   hj_col = (const int*)d_in[12];
    const float* hj_val = (const float*)d_in[13];
    const int*   hp_row = (const int*)d_in[14];
    const int*   hp_col = (const int*)d_in[15];
    const float* hp_val = (const float*)d_in[16];
    const int*   inter_row = (const int*)d_in[17];
    const int*   inter_col = (const int*)d_in[18];
    const float* inter_val = (const float*)d_in[19];

    const int NNZ_H = in_sizes[8];
    const int NNZ_I = in_sizes[17];

    float* out = (float*)d_out;
    const ll O_ITEM = S;
    const ll O_SG0 = S + SI;
    const ll O_SG1 = 2 * S + SI;
    const ll O_SG2 = 3 * S + SI;

    float*  gb; cudaGetSymbolAddress((void**)&gb, g_buf);
    __half* gh; cudaGetSymbolAddress((void**)&gh, g_h);
    int*   off; cudaGetSymbolAddress((void**)&off, g_off);
    int*   cnt; cudaGetSymbolAddress((void**)&cnt, g_cnt);
    int*   rk;  cudaGetSymbolAddress((void**)&rk, g_rank);
    int2*  pr;  cudaGetSymbolAddress((void**)&pr, g_pair);

    // side stream for the CSR build branch (created once, on the first —
    // non-capturing — call; reused by the capture call)
    static cudaStream_t sB = nullptr;
    static cudaEvent_t evRoot = nullptr, evB = nullptr;
    if (sB == nullptr) {
        cudaStreamCreateWithFlags(&sB, cudaStreamNonBlocking);
        cudaEventCreateWithFlags(&evRoot, cudaEventDisableTiming);
        cudaEventCreateWithFlags(&evB, cudaEventDisableTiming);
    }

    const int BS = 256;

    Build5 B;
    B.row[0] = hs_row;    B.col[0] = hs_col;    B.val[0] = hs_val;    B.nnz[0] = NNZ_H;
    B.row[1] = hj_row;    B.col[1] = hj_col;    B.val[1] = hj_val;    B.nnz[1] = NNZ_H;
    B.row[2] = hp_row;    B.col[2] = hp_col;    B.val[2] = hp_val;    B.nnz[2] = NNZ_H;
    B.row[3] = inter_row; B.col[3] = inter_col; B.val[3] = inter_val; B.nnz[3] = NNZ_I;
    B.row[4] = inter_col; B.col[4] = inter_row; B.val[4] = inter_val; B.nnz[4] = NNZ_I;
    ll po = 0, ro = 0;
    for (int m = 0; m < 5; ++m) {
        B.cnt[m] = cnt + m * (NU + 1);
        B.off[m] = off + m * (NU + 1);
        B.pair[m] = pr + po;  po += B.nnz[m];
        B.rank[m] = rk + ro;  ro += B.nnz[m];
    }

    // fork: build branch runs on sB concurrently with the dense prologue
    cudaEventRecord(evRoot, 0);
    cudaStreamWaitEvent(sB, evRoot, 0);

    // ---- branch B (side stream): CSR build ----
    int bpr = blocks_for((NNZ_H + 3) / 4, BS);
    zero_int_kernel<<<blocks_for(OFFLEN, BS), BS, 0, sB>>>(cnt, OFFLEN);
    hist5_kernel<<<5 * bpr, BS, 0, sB>>>(B, bpr);
    scan_kernel<<<5, 1024, 0, sB>>>();
    scat5_kernel<<<5 * bpr, BS, 0, sB>>>(B, bpr);
    cudaEventRecord(evB, sB);

    // ---- branch A (default stream): dense prologue ----
    compute_v_kernel<<<1, 64>>>(att_mat, att_agg);
    item_h_kernel<<<blocks_for(SI / 2, BS), BS>>>(item_emb, gh + XIT, (int)(SI / 2));
    cudaMemcpyAsync(out + O_ITEM, item_emb, SI * sizeof(float), cudaMemcpyDeviceToDevice, 0);

    dim3 gdim(64, 4);
    dim3 ggrid4((NU + 31) / 32, 4);
    gating_kernel<<<ggrid4, gdim>>>(user_emb, gating_w, gating_b, NU,
                                    gb + ACC0, gb + ACC1, gb + ACC2, gb + ACCS,
                                    gh + XG0, gh + XG1, gh + XG2, gh + XGS);

    const int uwb = blocks_for((ll)NU * 32, BS);
    attn_h_kernel<<<uwb, BS>>>(gh + XG0, gh + XG1, gh + XG2, gh + XGS, gb + VOFF,
                               gh + XMIX, NU);

    // join: SpMM needs both branches
    cudaStreamWaitEvent(0, evB, 0);

    const ll TOTW = 4ll * NU + NI;
    const int swb = blocks_for(TOTW * 32, BS);

    // ---- layer 1 ----
    Spmm5 A1;
    A1.off[0] = B.off[0]; A1.pair[0] = B.pair[0]; A1.x[0] = gh + XG0; A1.y[0] = gh + XT0; A1.acc[0] = gb + ACC0;
    A1.off[1] = B.off[1]; A1.pair[1] = B.pair[1]; A1.x[1] = gh + XG1; A1.y[1] = gh + XT1; A1.acc[1] = gb + ACC1;
    A1.off[2] = B.off[2]; A1.pair[2] = B.pair[2]; A1.x[2] = gh + XG2; A1.y[2] = gh + XT2; A1.acc[2] = gb + ACC2;
    A1.off[3] = B.off[4]; A1.pair[3] = B.pair[4]; A1.x[3] = gh + XMIX; A1.y[3] = gh + XITA; A1.acc[3] = out + O_ITEM;
    A1.off[4] = B.off[3]; A1.pair[4] = B.pair[3]; A1.x[4] = gh + XIT; A1.y[4] = gh + XUS; A1.acc[4] = gb + ACCS;
    spmm5_kernel<<<swb, BS>>>(A1);

    // ---- layer 2 ----
    attn_h_kernel<<<uwb, BS>>>(gh + XT0, gh + XT1, gh + XT2, gh + XUS, gb + VOFF,
                               gh + XMIX, NU);
    Spmm5 A2;
    A2.off[0] = B.off[0]; A2.pair[0] = B.pair[0]; A2.x[0] = gh + XT0; A2.y[0] = nullptr; A2.acc[0] = gb + ACC0;
    A2.off[1] = B.off[1]; A2.pair[1] = B.pair[1]; A2.x[1] = gh + XT1; A2.y[1] = nullptr; A2.acc[1] = gb + ACC1;
    A2.off[2] = B.off[2]; A2.pair[2] = B.pair[2]; A2.x[2] = gh + XT2; A2.y[2] = nullptr; A2.acc[2] = gb + ACC2;
    A2.off[3] = B.off[4]; A2.pair[3] = B.pair[4]; A2.x[3] = gh + XMIX; A2.y[3] = nullptr; A2.acc[3] = out + O_ITEM;
    A2.off[4] = B.off[3]; A2.pair[4] = B.pair[3]; A2.x[4] = gh + XITA; A2.y[4] = nullptr; A2.acc[4] = gb + ACCS;
    spmm5_kernel<<<swb, BS>>>(A2);

    // ---- final ----
    attn_f_kernel<<<uwb, BS>>>(gb + ACC0, gb + ACC1, gb + ACC2, gb + ACCS, gb + VOFF,
                               out, NU);
    dim3 ggrid3((NU + 31) / 32, 3);
    gating_kernel<<<ggrid3, gdim>>>(out, sgating_w, sgating_b, NU,
                                    out + O_SG0, out + O_SG1, out + O_SG2, nullptr,
                                    nullptr, nullptr, nullptr, nullptr);
}

// round 10
// speedup vs baseline: 4.2909x; 1.0004x over previous
#include <cuda_runtime.h>
#include <cuda_fp16.h>
#include <math.h>

#define NU 100000
#define NI 50000
#define DD 64
#define EPSV 1e-12f
#define MAXH 3200000
#define MAXI 3000000

typedef long long ll;

static constexpr ll S  = (ll)NU * DD;
static constexpr ll SI = (ll)NI * DD;

// fp32 scratch: 4 accumulators + v vector
static constexpr ll ACC0 = 0;
static constexpr ll ACC1 = 1 * S;
static constexpr ll ACC2 = 2 * S;
static constexpr ll ACCS = 3 * S;
static constexpr ll VOFF = 4 * S;
static constexpr ll TOT32 = VOFF + 64;
__device__ float g_buf[TOT32];

// fp16 gather-format scratch
static constexpr ll XG0 = 0;
static constexpr ll XG1 = 1 * S;
static constexpr ll XG2 = 2 * S;
static constexpr ll XGS = 3 * S;
static constexpr ll XT0 = 4 * S;
static constexpr ll XT1 = 5 * S;
static constexpr ll XT2 = 6 * S;
static constexpr ll XUS = 7 * S;
static constexpr ll XMIX = 8 * S;
static constexpr ll XIT  = 9 * S;
static constexpr ll XITA = 9 * S + SI;
static constexpr ll TOT16 = 9 * S + 2 * SI;
__device__ __half g_h[TOT16];

// CSR scratch
static constexpr int OFFLEN = 4 * (NU + 1) + (NI + 1);
__device__ int   g_off[OFFLEN];
__device__ int   g_cnt[OFFLEN];
__device__ short g_rank[3 * (ll)MAXH + 2 * (ll)MAXI];
__device__ int2  g_pair[3 * (ll)MAXH + 2 * (ll)MAXI];

struct Build5 {
    const int* row[5]; const int* col[5]; const float* val[5];
    short* rank[5]; int* cnt[5]; const int* off[5]; int2* pair[5]; int nnz[5];
};
struct Spmm5 { const int* off[5]; const int2* pair[5];
               const __half* x[5]; __half* y[5]; float* acc[5]; };

// ---------------------------------------------------------------------------
__device__ __forceinline__ float warp_sum(float v) {
#pragma unroll
    for (int o = 16; o > 0; o >>= 1) v += __shfl_xor_sync(0xFFFFFFFFu, v, o);
    return v;
}

// ---------------------------------------------------------------------------
__global__ void zero_int_kernel(int* p, int n) {
    int i = blockIdx.x * blockDim.x + threadIdx.x;
    if (i < n) p[i] = 0;
}

// fused 5-region histogram, 8 edges/thread (2 up-front int4 loads), short ranks
__global__ void hist5_kernel(Build5 b, int bpr) {
    int region = blockIdx.x / bpr;
    int bb = blockIdx.x - region * bpr;
    int nnz = b.nnz[region];
    const int* __restrict__ row = b.row[region];
    short* __restrict__ rank = b.rank[region];
    int* cnt = b.cnt[region];
    int i = (bb * 256 + threadIdx.x) * 8;
    if (i + 7 < nnz) {
        int4 r0 = *(const int4*)(row + i);
        int4 r1 = *(const int4*)(row + i + 4);
        int k0 = atomicAdd(cnt + r0.x, 1);
        int k1 = atomicAdd(cnt + r0.y, 1);
        int k2 = atomicAdd(cnt + r0.z, 1);
        int k3 = atomicAdd(cnt + r0.w, 1);
        int k4 = atomicAdd(cnt + r1.x, 1);
        int k5 = atomicAdd(cnt + r1.y, 1);
        int k6 = atomicAdd(cnt + r1.z, 1);
        int k7 = atomicAdd(cnt + r1.w, 1);
        short2 s0 = make_short2((short)k0, (short)k1);
        short2 s1 = make_short2((short)k2, (short)k3);
        short2 s2 = make_short2((short)k4, (short)k5);
        short2 s3 = make_short2((short)k6, (short)k7);
        int4 packed;
        packed.x = *(int*)&s0; packed.y = *(int*)&s1;
        packed.z = *(int*)&s2; packed.w = *(int*)&s3;
        *(int4*)(rank + i) = packed;
    } else {
        for (int j = i; j < nnz; ++j)
            rank[j] = (short)atomicAdd(cnt + __ldg(row + j), 1);
    }
}

// one block per region; chunked exclusive scan of counts -> off
__global__ void scan_kernel() {
    int region = blockIdx.x;
    int n = (region == 4) ? NI : NU;
    int base = region * (NU + 1);
    int* cnt = g_cnt + base;
    int* off = g_off + base;
    const int T = 1024;
    int t = threadIdx.x;
    int chunk = (n + T - 1) / T;
    int lo = t * chunk;
    int hi = lo + chunk; if (hi > n) hi = n;
    int sum = 0;
    for (int i = lo; i < hi; ++i) sum += cnt[i];

    __shared__ int ws[32];
    int lane = t & 31, wid = t >> 5;
    int x = sum;
#pragma unroll
    for (int o = 1; o < 32; o <<= 1) {
        int y = __shfl_up_sync(0xFFFFFFFFu, x, o);
        if (lane >= o) x += y;
    }
    if (lane == 31) ws[wid] = x;
    __syncthreads();
    if (t < 32) {
        int y = ws[t];
#pragma unroll
        for (int o = 1; o < 32; o <<= 1) {
            int z = __shfl_up_sync(0xFFFFFFFFu, y, o);
            if (t >= o) y += z;
        }
        ws[t] = y;
    }
    __syncthreads();
    int pre = x - sum + ((wid > 0) ? ws[wid - 1] : 0);
    if (t == T - 1) off[n] = pre + sum;
    int run = pre;
    for (int i = lo; i < hi; ++i) {
        int v = cnt[i];
        off[i] = run;
        run += v;
    }
}

// fused 5-region scatter, 8 edges/thread, atomic-free via short rank
__global__ void scat5_kernel(Build5 b, int bpr) {
    int region = blockIdx.x / bpr;
    int bb = blockIdx.x - region * bpr;
    int nnz = b.nnz[region];
    const int* __restrict__ row = b.row[region];
    const int* __restrict__ col = b.col[region];
    const float* __restrict__ val = b.val[region];
    const short* __restrict__ rank = b.rank[region];
    const int* __restrict__ off = b.off[region];
    int2* __restrict__ pair = b.pair[region];
    int i = (bb * 256 + threadIdx.x) * 8;
    if (i + 7 < nnz) {
        int4 r0 = *(const int4*)(row + i);
        int4 r1 = *(const int4*)(row + i + 4);
        int4 c0 = *(const int4*)(col + i);
        int4 c1 = *(const int4*)(col + i + 4);
        float4 v0 = *(const float4*)(val + i);
        float4 v1 = *(const float4*)(val + i + 4);
        int4 kp = *(const int4*)(rank + i);
        short2 s0 = *(short2*)&kp.x, s1 = *(short2*)&kp.y;
        short2 s2 = *(short2*)&kp.z, s3 = *(short2*)&kp.w;
        pair[__ldg(off + r0.x) + s0.x] = make_int2(c0.x, __float_as_int(v0.x));
        pair[__ldg(off + r0.y) + s0.y] = make_int2(c0.y, __float_as_int(v0.y));
        pair[__ldg(off + r0.z) + s1.x] = make_int2(c0.z, __float_as_int(v0.z));
        pair[__ldg(off + r0.w) + s1.y] = make_int2(c0.w, __float_as_int(v0.w));
        pair[__ldg(off + r1.x) + s2.x] = make_int2(c1.x, __float_as_int(v1.x));
        pair[__ldg(off + r1.y) + s2.y] = make_int2(c1.y, __float_as_int(v1.y));
        pair[__ldg(off + r1.z) + s3.x] = make_int2(c1.z, __float_as_int(v1.z));
        pair[__ldg(off + r1.w) + s3.y] = make_int2(c1.w, __float_as_int(v1.w));
    } else {
        for (int j = i; j < nnz; ++j) {
            pair[__ldg(off + __ldg(row + j)) + __ldg(rank + j)] =
                make_int2(__ldg(col + j), __float_as_int(__ldg(val + j)));
        }
    }
}

// Fused 5-region CSR SpMM: one warp per row, cooperative pair loading via shfl,
// fp16 gathers, fp32 accumulate, fused l2norm-acc.
__global__ void spmm5_kernel(Spmm5 a) {
    ll gw = ((ll)blockIdx.x * blockDim.x + threadIdx.x) >> 5;
    int lane = threadIdx.x & 31;
    int region, row;
    if (gw < NU)                { region = 0; row = (int)gw; }
    else if (gw < 2 * NU)       { region = 1; row = (int)(gw - NU); }
    else if (gw < 3 * NU)       { region = 2; row = (int)(gw - 2 * NU); }
    else if (gw < 3 * NU + NI)  { region = 3; row = (int)(gw - 3 * NU); }
    else if (gw < 4 * NU + NI)  { region = 4; row = (int)(gw - 3 * NU - NI); }
    else return;

    const int* off = a.off[region];
    const int2* __restrict__ pair = a.pair[region];
    const __half* __restrict__ x16 = a.x[region];
    int s = __ldg(off + row), e = __ldg(off + row + 1);
    float ax = 0.f, ay = 0.f;
    int base = s;
    while (e - base >= 32) {
        int2 myp = __ldg(pair + base + lane);
#pragma unroll 8
        for (int j = 0; j < 32; ++j) {
            int c = __shfl_sync(0xFFFFFFFFu, myp.x, j);
            float v = __int_as_float(__shfl_sync(0xFFFFFFFFu, myp.y, j));
            float2 f = __half22float2(__ldg((const __half2*)(x16 + (ll)c * DD) + lane));
            ax = fmaf(v, f.x, ax); ay = fmaf(v, f.y, ay);
        }
        base += 32;
    }
    int rem = e - base;
    if (rem > 0) {
        int2 myp = (lane < rem) ? __ldg(pair + base + lane) : make_int2(0, 0);
        for (int j = 0; j < rem; ++j) {
            int c = __shfl_sync(0xFFFFFFFFu, myp.x, j);
            float v = __int_as_float(__shfl_sync(0xFFFFFFFFu, myp.y, j));
            float2 f = __half22float2(__ldg((const __half2*)(x16 + (ll)c * DD) + lane));
            ax = fmaf(v, f.x, ax); ay = fmaf(v, f.y, ay);
        }
    }

    __half* y16 = a.y[region];
    if (y16) ((__half2*)(y16 + (ll)row * DD))[lane] = __floats2half2_rn(ax, ay);
    float ss = warp_sum(ax * ax + ay * ay);
    float sc = 1.f / fmaxf(sqrtf(ss), EPSV);
    float* acc = a.acc[region];
    ll b2 = (ll)row * DD + lane * 2;
    float2 av = *(const float2*)(acc + b2);
    av.x = fmaf(ax, sc, av.x);
    av.y = fmaf(ay, sc, av.y);
    *(float2*)(acc + b2) = av;
}

// v[d] = sum_j att_mat[d][j] * att_agg[j]
__global__ void compute_v_kernel(const float* __restrict__ att_mat,
                                 const float* __restrict__ att_agg) {
    int d = threadIdx.x;
    float s = 0.f;
#pragma unroll
    for (int j = 0; j < DD; ++j) s = fmaf(att_mat[d * DD + j], att_agg[j], s);
    g_buf[VOFF + d] = s;
}

__global__ void item_h_kernel(const float* __restrict__ src, __half* __restrict__ dst, int n2) {
    int i = blockIdx.x * blockDim.x + threadIdx.x;
    if (i < n2) {
        float2 v = ((const float2*)src)[i];
        ((__half2*)dst)[i] = __floats2half2_rn(v.x, v.y);
    }
}

// attention over fp16 inputs -> fp16 mixed (v precomputed in g_buf)
__global__ void attn_h_kernel(const __half* __restrict__ c0p, const __half* __restrict__ c1p,
                              const __half* __restrict__ c2p, const __half* __restrict__ othp,
                              const float* __restrict__ v,
                              __half* __restrict__ out, int n_rows) {
    int w = (int)(((ll)blockIdx.x * blockDim.x + threadIdx.x) >> 5);
    if (w >= n_rows) return;
    int lane = threadIdx.x & 31;
    ll rb = (ll)w * DD;
    float2 c0 = __half22float2(((const __half2*)(c0p + rb))[lane]);
    float2 c1 = __half22float2(((const __half2*)(c1p + rb))[lane]);
    float2 c2 = __half22float2(((const __half2*)(c2p + rb))[lane]);
    float2 ot = __half22float2(((const __half2*)(othp + rb))[lane]);
    float2 vv = *(const float2*)(v + lane * 2);
    float w0 = warp_sum(c0.x * vv.x + c0.y * vv.y);
    float w1 = warp_sum(c1.x * vv.x + c1.y * vv.y);
    float w2 = warp_sum(c2.x * vv.x + c2.y * vv.y);
    float m = fmaxf(w0, fmaxf(w1, w2));
    float e0 = __expf(w0 - m), e1 = __expf(w1 - m), e2 = __expf(w2 - m);
    float inv = 1.f / (e0 + e1 + e2);
    float s0 = e0 * inv, s1 = e1 * inv, s2 = e2 * inv;
    float ox = 0.5f * (s0 * c0.x + s1 * c1.x + s2 * c2.x) + 0.5f * ot.x;
    float oy = 0.5f * (s0 * c0.y + s1 * c1.y + s2 * c2.y) + 0.5f * ot.y;
    ((__half2*)(out + rb))[lane] = __floats2half2_rn(ox, oy);
}

// final attention over fp32 accumulators -> fp32 out
__global__ void attn_f_kernel(const float* __restrict__ c0p, const float* __restrict__ c1p,
                              const float* __restrict__ c2p, const float* __restrict__ othp,
                              const float* __restrict__ v,
                              float* __restrict__ out, int n_rows) {
    int w = (int)(((ll)blockIdx.x * blockDim.x + threadIdx.x) >> 5);
    if (w >= n_rows) return;
    int lane = threadIdx.x & 31;
    ll base = (ll)w * DD + lane * 2;
    float2 c0 = *(const float2*)(c0p + base);
    float2 c1 = *(const float2*)(c1p + base);
    float2 c2 = *(const float2*)(c2p + base);
    float2 ot = *(const float2*)(othp + base);
    float2 vv = *(const float2*)(v + lane * 2);
    float w0 = warp_sum(c0.x * vv.x + c0.y * vv.y);
    float w1 = warp_sum(c1.x * vv.x + c1.y * vv.y);
    float w2 = warp_sum(c2.x * vv.x + c2.y * vv.y);
    float m = fmaxf(w0, fmaxf(w1, w2));
    float e0 = __expf(w0 - m), e1 = __expf(w1 - m), e2 = __expf(w2 - m);
    float inv = 1.f / (e0 + e1 + e2);
    float s0 = e0 * inv, s1 = e1 * inv, s2 = e2 * inv;
    float ox = (s0 * c0.x + s1 * c1.x + s2 * c2.x) + 0.5f * ot.x;
    float oy = (s0 * c0.y + s1 * c1.y + s2 * c2.y) + 0.5f * ot.y;
    *(float2*)(out + base) = make_float2(ox, oy);
}

// self-gating, float4 LDS inner loop; ONE gate per block (blockIdx.y = gate)
__global__ void gating_kernel(const float* __restrict__ in, const float* __restrict__ W,
                              const float* __restrict__ B, int n_rows,
                              float* o0, float* o1, float* o2, float* o3,
                              __half* h0, __half* h1, __half* h2, __half* h3) {
    __shared__ float sW[DD * DD];
    __shared__ float se[32 * DD];
    int g = blockIdx.y;
    int tx = threadIdx.x, ty = threadIdx.y;
    int tid = ty * 64 + tx;
    int row0 = blockIdx.x * 32;
    for (int i = tid; i < 32 * DD; i += 256) {
        int r = i >> 6, c = i & 63;
        int gr = row0 + r;
        se[i] = (gr < n_rows) ? in[(ll)gr * DD + c] : 0.f;
    }
    for (int i = tid; i < DD * DD; i += 256) sW[i] = W[(ll)g * DD * DD + i];
    __syncthreads();

    float* outs[4] = {o0, o1, o2, o3};
    __half* houts[4] = {h0, h1, h2, h3};
    float* og = outs[g];
    __half* hg = houts[g];

    float bg = B[g * DD + tx];
    float acc[8] = {0, 0, 0, 0, 0, 0, 0, 0};
#pragma unroll
    for (int d4 = 0; d4 < DD; d4 += 4) {
        float w0 = sW[(d4 + 0) * DD + tx];
        float w1 = sW[(d4 + 1) * DD + tx];
        float w2 = sW[(d4 + 2) * DD + tx];
        float w3 = sW[(d4 + 3) * DD + tx];
#pragma unroll
        for (int rr = 0; rr < 8; ++rr) {
            float4 s4 = *(const float4*)(se + (ty + 4 * rr) * DD + d4);
            acc[rr] = fmaf(s4.x, w0, acc[rr]);
            acc[rr] = fmaf(s4.y, w1, acc[rr]);
            acc[rr] = fmaf(s4.z, w2, acc[rr]);
            acc[rr] = fmaf(s4.w, w3, acc[rr]);
        }
    }
#pragma unroll
    for (int rr = 0; rr < 8; ++rr) {
        int r = ty + 4 * rr;
        int gr = row0 + r;
        if (gr < n_rows) {
            float z = acc[rr] + bg;
            float sig = 1.f / (1.f + __expf(-z));
            float ov = se[r * DD + tx] * sig;
            ll idx = (ll)gr * DD + tx;
            if (og) og[idx] = ov;
            if (hg) hg[idx] = __float2half(ov);
        }
    }
}

// ---------------------------------------------------------------------------
static inline int blocks_for(ll threads, int bs) { return (int)((threads + bs - 1) / bs); }

extern "C" void kernel_launch(void* const* d_in, const int* in_sizes, int n_in,
                              void* d_out, int out_size) {
    const float* user_emb  = (const float*)d_in[0];
    const float* item_emb  = (const float*)d_in[1];
    const float* gating_w  = (const float*)d_in[2];
    const float* gating_b  = (const float*)d_in[3];
    const float* sgating_w = (const float*)d_in[4];
    const float* sgating_b = (const float*)d_in[5];
    const float* att_mat   = (const float*)d_in[6];
    const float* att_agg   = (const float*)d_in[7];
    const int*   hs_row = (const int*)d_in[8];
    const int*   hs_col = (const int*)d_in[9];
    const float* hs_val = (const float*)d_in[10];
    const int*   hj_row = (const int*)d_in[11];
    const int*   hj_col = (const int*)d_in[12];
    const float* hj_val = (const float*)d_in[13];
    const int*   hp_row = (const int*)d_in[14];
    const int*   hp_col = (const int*)d_in[15];
    const float* hp_val = (const float*)d_in[16];
    const int*   inter_row = (const int*)d_in[17];
    const int*   inter_col = (const int*)d_in[18];
    const float* inter_val = (const float*)d_in[19];

    const int NNZ_H = in_sizes[8];
    const int NNZ_I = in_sizes[17];

    float* out = (float*)d_out;
    const ll O_ITEM = S;
    const ll O_SG0 = S + SI;
    const ll O_SG1 = 2 * S + SI;
    const ll O_SG2 = 3 * S + SI;

    float*  gb; cudaGetSymbolAddress((void**)&gb, g_buf);
    __half* gh; cudaGetSymbolAddress((void**)&gh, g_h);
    int*   off; cudaGetSymbolAddress((void**)&off, g_off);
    int*   cnt; cudaGetSymbolAddress((void**)&cnt, g_cnt);
    short* rk;  cudaGetSymbolAddress((void**)&rk, g_rank);
    int2*  pr;  cudaGetSymbolAddress((void**)&pr, g_pair);

    static cudaStream_t sB = nullptr;
    static cudaEvent_t evRoot = nullptr, evB = nullptr;
    if (sB == nullptr) {
        cudaStreamCreateWithFlags(&sB, cudaStreamNonBlocking);
        cudaEventCreateWithFlags(&evRoot, cudaEventDisableTiming);
        cudaEventCreateWithFlags(&evB, cudaEventDisableTiming);
    }

    const int BS = 256;

    Build5 B;
    B.row[0] = hs_row;    B.col[0] = hs_col;    B.val[0] = hs_val;    B.nnz[0] = NNZ_H;
    B.row[1] = hj_row;    B.col[1] = hj_col;    B.val[1] = hj_val;    B.nnz[1] = NNZ_H;
    B.row[2] = hp_row;    B.col[2] = hp_col;    B.val[2] = hp_val;    B.nnz[2] = NNZ_H;
    B.row[3] = inter_row; B.col[3] = inter_col; B.val[3] = inter_val; B.nnz[3] = NNZ_I;
    B.row[4] = inter_col; B.col[4] = inter_row; B.val[4] = inter_val; B.nnz[4] = NNZ_I;
    ll po = 0, ro = 0;
    for (int m = 0; m < 5; ++m) {
        B.cnt[m] = cnt + m * (NU + 1);
        B.off[m] = off + m * (NU + 1);
        B.pair[m] = pr + po;  po += B.nnz[m];
        B.rank[m] = rk + ro;  ro += B.nnz[m];
    }

    // fork: build branch runs on sB concurrently with the dense prologue
    cudaEventRecord(evRoot, 0);
    cudaStreamWaitEvent(sB, evRoot, 0);

    // ---- branch B (side stream): CSR build ----
    int bpr = blocks_for((NNZ_H + 7) / 8, BS);
    zero_int_kernel<<<blocks_for(OFFLEN, BS), BS, 0, sB>>>(cnt, OFFLEN);
    hist5_kernel<<<5 * bpr, BS, 0, sB>>>(B, bpr);
    scan_kernel<<<5, 1024, 0, sB>>>();
    scat5_kernel<<<5 * bpr, BS, 0, sB>>>(B, bpr);
    cudaEventRecord(evB, sB);

    // ---- branch A (default stream): dense prologue ----
    compute_v_kernel<<<1, 64>>>(att_mat, att_agg);
    item_h_kernel<<<blocks_for(SI / 2, BS), BS>>>(item_emb, gh + XIT, (int)(SI / 2));
    cudaMemcpyAsync(out + O_ITEM, item_emb, SI * sizeof(float), cudaMemcpyDeviceToDevice, 0);

    dim3 gdim(64, 4);
    dim3 ggrid4((NU + 31) / 32, 4);
    gating_kernel<<<ggrid4, gdim>>>(user_emb, gating_w, gating_b, NU,
                                    gb + ACC0, gb + ACC1, gb + ACC2, gb + ACCS,
                                    gh + XG0, gh + XG1, gh + XG2, gh + XGS);

    const int uwb = blocks_for((ll)NU * 32, BS);
    attn_h_kernel<<<uwb, BS>>>(gh + XG0, gh + XG1, gh + XG2, gh + XGS, gb + VOFF,
                               gh + XMIX, NU);

    // join: SpMM needs both branches
    cudaStreamWaitEvent(0, evB, 0);

    const ll TOTW = 4ll * NU + NI;
    const int swb = blocks_for(TOTW * 32, BS);

    // ---- layer 1 ----
    Spmm5 A1;
    A1.off[0] = B.off[0]; A1.pair[0] = B.pair[0]; A1.x[0] = gh + XG0; A1.y[0] = gh + XT0; A1.acc[0] = gb + ACC0;
    A1.off[1] = B.off[1]; A1.pair[1] = B.pair[1]; A1.x[1] = gh + XG1; A1.y[1] = gh + XT1; A1.acc[1] = gb + ACC1;
    A1.off[2] = B.off[2]; A1.pair[2] = B.pair[2]; A1.x[2] = gh + XG2; A1.y[2] = gh + XT2; A1.acc[2] = gb + ACC2;
    A1.off[3] = B.off[4]; A1.pair[3] = B.pair[4]; A1.x[3] = gh + XMIX; A1.y[3] = gh + XITA; A1.acc[3] = out + O_ITEM;
    A1.off[4] = B.off[3]; A1.pair[4] = B.pair[3]; A1.x[4] = gh + XIT; A1.y[4] = gh + XUS; A1.acc[4] = gb + ACCS;
    spmm5_kernel<<<swb, BS>>>(A1);

    // ---- layer 2 ----
    attn_h_kernel<<<uwb, BS>>>(gh + XT0, gh + XT1, gh + XT2, gh + XUS, gb + VOFF,
                               gh + XMIX, NU);
    Spmm5 A2;
    A2.off[0] = B.off[0]; A2.pair[0] = B.pair[0]; A2.x[0] = gh + XT0; A2.y[0] = nullptr; A2.acc[0] = gb + ACC0;
    A2.off[1] = B.off[1]; A2.pair[1] = B.pair[1]; A2.x[1] = gh + XT1; A2.y[1] = nullptr; A2.acc[1] = gb + ACC1;
    A2.off[2] = B.off[2]; A2.pair[2] = B.pair[2]; A2.x[2] = gh + XT2; A2.y[2] = nullptr; A2.acc[2] = gb + ACC2;
    A2.off[3] = B.off[4]; A2.pair[3] = B.pair[4]; A2.x[3] = gh + XMIX; A2.y[3] = nullptr; A2.acc[3] = out + O_ITEM;
    A2.off[4] = B.off[3]; A2.pair[4] = B.pair[3]; A2.x[4] = gh + XITA; A2.y[4] = nullptr; A2.acc[4] = gb + ACCS;
    spmm5_kernel<<<swb, BS>>>(A2);

    // ---- final ----
    attn_f_kernel<<<uwb, BS>>>(gb + ACC0, gb + ACC1, gb + ACC2, gb + ACCS, gb + VOFF,
                               out, NU);
    dim3 ggrid3((NU + 31) / 32, 3);
    gating_kernel<<<ggrid3, gdim>>>(out, sgating_w, sgating_b, NU,
                                    out + O_SG0, out + O_SG1, out + O_SG2, nullptr,
                                    nullptr, nullptr, nullptr, nullptr);
}

// round 11
// speedup vs baseline: 4.2933x; 1.0006x over previous
#include <cuda_runtime.h>
#include <cuda_fp16.h>
#include <math.h>

#define NU 100000
#define NI 50000
#define DD 64
#define EPSV 1e-12f
#define MAXH 3200000
#define MAXI 3000000

typedef long long ll;

static constexpr ll S  = (ll)NU * DD;
static constexpr ll SI = (ll)NI * DD;

// fp32 scratch: 4 accumulators + v vector
static constexpr ll ACC0 = 0;
static constexpr ll ACC1 = 1 * S;
static constexpr ll ACC2 = 2 * S;
static constexpr ll ACCS = 3 * S;
static constexpr ll VOFF = 4 * S;
static constexpr ll TOT32 = VOFF + 64;
__device__ float g_buf[TOT32];

// fp16 gather-format scratch
static constexpr ll XG0 = 0;
static constexpr ll XG1 = 1 * S;
static constexpr ll XG2 = 2 * S;
static constexpr ll XGS = 3 * S;
static constexpr ll XT0 = 4 * S;
static constexpr ll XT1 = 5 * S;
static constexpr ll XT2 = 6 * S;
static constexpr ll XUS = 7 * S;
static constexpr ll XMIX = 8 * S;
static constexpr ll XIT  = 9 * S;
static constexpr ll XITA = 9 * S + SI;
static constexpr ll TOT16 = 9 * S + 2 * SI;
__device__ __half g_h[TOT16];

// CSR scratch
static constexpr int OFFLEN = 4 * (NU + 1) + (NI + 1);
__device__ int   g_off[OFFLEN];
__device__ int   g_cnt[OFFLEN];
__device__ short g_rank[3 * (ll)MAXH + 2 * (ll)MAXI];
__device__ int2  g_pair[3 * (ll)MAXH + 2 * (ll)MAXI];

struct Build5 {
    const int* row[5]; const int* col[5]; const float* val[5];
    short* rank[5]; int* cnt[5]; const int* off[5]; int2* pair[5]; int nnz[5];
};
struct Spmm5 { const int* off[5]; const int2* pair[5];
               const __half* x[5]; __half* y[5]; float* acc[5]; };

// ---------------------------------------------------------------------------
__device__ __forceinline__ float warp_sum(float v) {
#pragma unroll
    for (int o = 16; o > 0; o >>= 1) v += __shfl_xor_sync(0xFFFFFFFFu, v, o);
    return v;
}

// ---------------------------------------------------------------------------
__global__ void zero_int_kernel(int* p, int n) {
    int i = blockIdx.x * blockDim.x + threadIdx.x;
    if (i < n) p[i] = 0;
}

// fused 5-region histogram, 8 edges/thread (2 up-front int4 loads), short ranks
__global__ void hist5_kernel(Build5 b, int bpr) {
    int region = blockIdx.x / bpr;
    int bb = blockIdx.x - region * bpr;
    int nnz = b.nnz[region];
    const int* __restrict__ row = b.row[region];
    short* __restrict__ rank = b.rank[region];
    int* cnt = b.cnt[region];
    int i = (bb * 256 + threadIdx.x) * 8;
    if (i + 7 < nnz) {
        int4 r0 = *(const int4*)(row + i);
        int4 r1 = *(const int4*)(row + i + 4);
        int k0 = atomicAdd(cnt + r0.x, 1);
        int k1 = atomicAdd(cnt + r0.y, 1);
        int k2 = atomicAdd(cnt + r0.z, 1);
        int k3 = atomicAdd(cnt + r0.w, 1);
        int k4 = atomicAdd(cnt + r1.x, 1);
        int k5 = atomicAdd(cnt + r1.y, 1);
        int k6 = atomicAdd(cnt + r1.z, 1);
        int k7 = atomicAdd(cnt + r1.w, 1);
        short2 s0 = make_short2((short)k0, (short)k1);
        short2 s1 = make_short2((short)k2, (short)k3);
        short2 s2 = make_short2((short)k4, (short)k5);
        short2 s3 = make_short2((short)k6, (short)k7);
        int4 packed;
        packed.x = *(int*)&s0; packed.y = *(int*)&s1;
        packed.z = *(int*)&s2; packed.w = *(int*)&s3;
        *(int4*)(rank + i) = packed;
    } else {
        for (int j = i; j < nnz; ++j)
            rank[j] = (short)atomicAdd(cnt + __ldg(row + j), 1);
    }
}

// one block per region; chunked exclusive scan of counts -> off
__global__ void scan_kernel() {
    int region = blockIdx.x;
    int n = (region == 4) ? NI : NU;
    int base = region * (NU + 1);
    int* cnt = g_cnt + base;
    int* off = g_off + base;
    const int T = 1024;
    int t = threadIdx.x;
    int chunk = (n + T - 1) / T;
    int lo = t * chunk;
    int hi = lo + chunk; if (hi > n) hi = n;
    int sum = 0;
    for (int i = lo; i < hi; ++i) sum += cnt[i];

    __shared__ int ws[32];
    int lane = t & 31, wid = t >> 5;
    int x = sum;
#pragma unroll
    for (int o = 1; o < 32; o <<= 1) {
        int y = __shfl_up_sync(0xFFFFFFFFu, x, o);
        if (lane >= o) x += y;
    }
    if (lane == 31) ws[wid] = x;
    __syncthreads();
    if (t < 32) {
        int y = ws[t];
#pragma unroll
        for (int o = 1; o < 32; o <<= 1) {
            int z = __shfl_up_sync(0xFFFFFFFFu, y, o);
            if (t >= o) y += z;
        }
        ws[t] = y;
    }
    __syncthreads();
    int pre = x - sum + ((wid > 0) ? ws[wid - 1] : 0);
    if (t == T - 1) off[n] = pre + sum;
    int run = pre;
    for (int i = lo; i < hi; ++i) {
        int v = cnt[i];
        off[i] = run;
        run += v;
    }
}

// fused 5-region scatter, 8 edges/thread, atomic-free via short rank
__global__ void scat5_kernel(Build5 b, int bpr) {
    int region = blockIdx.x / bpr;
    int bb = blockIdx.x - region * bpr;
    int nnz = b.nnz[region];
    const int* __restrict__ row = b.row[region];
    const int* __restrict__ col = b.col[region];
    const float* __restrict__ val = b.val[region];
    const short* __restrict__ rank = b.rank[region];
    const int* __restrict__ off = b.off[region];
    int2* __restrict__ pair = b.pair[region];
    int i = (bb * 256 + threadIdx.x) * 8;
    if (i + 7 < nnz) {
        int4 r0 = *(const int4*)(row + i);
        int4 r1 = *(const int4*)(row + i + 4);
        int4 c0 = *(const int4*)(col + i);
        int4 c1 = *(const int4*)(col + i + 4);
        float4 v0 = *(const float4*)(val + i);
        float4 v1 = *(const float4*)(val + i + 4);
        int4 kp = *(const int4*)(rank + i);
        short2 s0 = *(short2*)&kp.x, s1 = *(short2*)&kp.y;
        short2 s2 = *(short2*)&kp.z, s3 = *(short2*)&kp.w;
        pair[__ldg(off + r0.x) + s0.x] = make_int2(c0.x, __float_as_int(v0.x));
        pair[__ldg(off + r0.y) + s0.y] = make_int2(c0.y, __float_as_int(v0.y));
        pair[__ldg(off + r0.z) + s1.x] = make_int2(c0.z, __float_as_int(v0.z));
        pair[__ldg(off + r0.w) + s1.y] = make_int2(c0.w, __float_as_int(v0.w));
        pair[__ldg(off + r1.x) + s2.x] = make_int2(c1.x, __float_as_int(v1.x));
        pair[__ldg(off + r1.y) + s2.y] = make_int2(c1.y, __float_as_int(v1.y));
        pair[__ldg(off + r1.z) + s3.x] = make_int2(c1.z, __float_as_int(v1.z));
        pair[__ldg(off + r1.w) + s3.y] = make_int2(c1.w, __float_as_int(v1.w));
    } else {
        for (int j = i; j < nnz; ++j) {
            pair[__ldg(off + __ldg(row + j)) + __ldg(rank + j)] =
                make_int2(__ldg(col + j), __float_as_int(__ldg(val + j)));
        }
    }
}

// Fused 5-region CSR SpMM: one warp per row, cooperative pair loading via shfl,
// fp16 gathers, fp32 accumulate, fused l2norm-acc.
__global__ void spmm5_kernel(Spmm5 a) {
    ll gw = ((ll)blockIdx.x * blockDim.x + threadIdx.x) >> 5;
    int lane = threadIdx.x & 31;
    int region, row;
    if (gw < NU)                { region = 0; row = (int)gw; }
    else if (gw < 2 * NU)       { region = 1; row = (int)(gw - NU); }
    else if (gw < 3 * NU)       { region = 2; row = (int)(gw - 2 * NU); }
    else if (gw < 3 * NU + NI)  { region = 3; row = (int)(gw - 3 * NU); }
    else if (gw < 4 * NU + NI)  { region = 4; row = (int)(gw - 3 * NU - NI); }
    else return;

    const int* off = a.off[region];
    const int2* __restrict__ pair = a.pair[region];
    const __half* __restrict__ x16 = a.x[region];
    int s = __ldg(off + row), e = __ldg(off + row + 1);
    float ax = 0.f, ay = 0.f;
    int base = s;
    while (e - base >= 32) {
        int2 myp = __ldg(pair + base + lane);
#pragma unroll 8
        for (int j = 0; j < 32; ++j) {
            int c = __shfl_sync(0xFFFFFFFFu, myp.x, j);
            float v = __int_as_float(__shfl_sync(0xFFFFFFFFu, myp.y, j));
            float2 f = __half22float2(__ldg((const __half2*)(x16 + (ll)c * DD) + lane));
            ax = fmaf(v, f.x, ax); ay = fmaf(v, f.y, ay);
        }
        base += 32;
    }
    int rem = e - base;
    if (rem > 0) {
        int2 myp = (lane < rem) ? __ldg(pair + base + lane) : make_int2(0, 0);
        for (int j = 0; j < rem; ++j) {
            int c = __shfl_sync(0xFFFFFFFFu, myp.x, j);
            float v = __int_as_float(__shfl_sync(0xFFFFFFFFu, myp.y, j));
            float2 f = __half22float2(__ldg((const __half2*)(x16 + (ll)c * DD) + lane));
            ax = fmaf(v, f.x, ax); ay = fmaf(v, f.y, ay);
        }
    }

    __half* y16 = a.y[region];
    if (y16) ((__half2*)(y16 + (ll)row * DD))[lane] = __floats2half2_rn(ax, ay);
    float ss = warp_sum(ax * ax + ay * ay);
    float sc = 1.f / fmaxf(sqrtf(ss), EPSV);
    float* acc = a.acc[region];
    ll b2 = (ll)row * DD + lane * 2;
    float2 av = *(const float2*)(acc + b2);
    av.x = fmaf(ax, sc, av.x);
    av.y = fmaf(ay, sc, av.y);
    *(float2*)(acc + b2) = av;
}

// v[d] = sum_j att_mat[d][j] * att_agg[j]
__global__ void compute_v_kernel(const float* __restrict__ att_mat,
                                 const float* __restrict__ att_agg) {
    int d = threadIdx.x;
    float s = 0.f;
#pragma unroll
    for (int j = 0; j < DD; ++j) s = fmaf(att_mat[d * DD + j], att_agg[j], s);
    g_buf[VOFF + d] = s;
}

__global__ void item_h_kernel(const float* __restrict__ src, __half* __restrict__ dst, int n2) {
    int i = blockIdx.x * blockDim.x + threadIdx.x;
    if (i < n2) {
        float2 v = ((const float2*)src)[i];
        ((__half2*)dst)[i] = __floats2half2_rn(v.x, v.y);
    }
}

// attention over fp16 inputs -> fp16 mixed (v precomputed in g_buf)
__global__ void attn_h_kernel(const __half* __restrict__ c0p, const __half* __restrict__ c1p,
                              const __half* __restrict__ c2p, const __half* __restrict__ othp,
                              const float* __restrict__ v,
                              __half* __restrict__ out, int n_rows) {
    int w = (int)(((ll)blockIdx.x * blockDim.x + threadIdx.x) >> 5);
    if (w >= n_rows) return;
    int lane = threadIdx.x & 31;
    ll rb = (ll)w * DD;
    float2 c0 = __half22float2(((const __half2*)(c0p + rb))[lane]);
    float2 c1 = __half22float2(((const __half2*)(c1p + rb))[lane]);
    float2 c2 = __half22float2(((const __half2*)(c2p + rb))[lane]);
    float2 ot = __half22float2(((const __half2*)(othp + rb))[lane]);
    float2 vv = *(const float2*)(v + lane * 2);
    float w0 = warp_sum(c0.x * vv.x + c0.y * vv.y);
    float w1 = warp_sum(c1.x * vv.x + c1.y * vv.y);
    float w2 = warp_sum(c2.x * vv.x + c2.y * vv.y);
    float m = fmaxf(w0, fmaxf(w1, w2));
    float e0 = __expf(w0 - m), e1 = __expf(w1 - m), e2 = __expf(w2 - m);
    float inv = 1.f / (e0 + e1 + e2);
    float s0 = e0 * inv, s1 = e1 * inv, s2 = e2 * inv;
    float ox = 0.5f * (s0 * c0.x + s1 * c1.x + s2 * c2.x) + 0.5f * ot.x;
    float oy = 0.5f * (s0 * c0.y + s1 * c1.y + s2 * c2.y) + 0.5f * ot.y;
    ((__half2*)(out + rb))[lane] = __floats2half2_rn(ox, oy);
}

// final attention over fp32 accumulators -> fp32 out
__global__ void attn_f_kernel(const float* __restrict__ c0p, const float* __restrict__ c1p,
                              const float* __restrict__ c2p, const float* __restrict__ othp,
                              const float* __restrict__ v,
                              float* __restrict__ out, int n_rows) {
    int w = (int)(((ll)blockIdx.x * blockDim.x + threadIdx.x) >> 5);
    if (w >= n_rows) return;
    int lane = threadIdx.x & 31;
    ll base = (ll)w * DD + lane * 2;
    float2 c0 = *(const float2*)(c0p + base);
    float2 c1 = *(const float2*)(c1p + base);
    float2 c2 = *(const float2*)(c2p + base);
    float2 ot = *(const float2*)(othp + base);
    float2 vv = *(const float2*)(v + lane * 2);
    float w0 = warp_sum(c0.x * vv.x + c0.y * vv.y);
    float w1 = warp_sum(c1.x * vv.x + c1.y * vv.y);
    float w2 = warp_sum(c2.x * vv.x + c2.y * vv.y);
    float m = fmaxf(w0, fmaxf(w1, w2));
    float e0 = __expf(w0 - m), e1 = __expf(w1 - m), e2 = __expf(w2 - m);
    float inv = 1.f / (e0 + e1 + e2);
    float s0 = e0 * inv, s1 = e1 * inv, s2 = e2 * inv;
    float ox = (s0 * c0.x + s1 * c1.x + s2 * c2.x) + 0.5f * ot.x;
    float oy = (s0 * c0.y + s1 * c1.y + s2 * c2.y) + 0.5f * ot.y;
    *(float2*)(out + base) = make_float2(ox, oy);
}

// self-gating, float4 LDS inner loop; ONE gate per block (blockIdx.y = gate)
__global__ void gating_kernel(const float* __restrict__ in, const float* __restrict__ W,
                              const float* __restrict__ B, int n_rows,
                              float* o0, float* o1, float* o2, float* o3,
                              __half* h0, __half* h1, __half* h2, __half* h3) {
    __shared__ float sW[DD * DD];
    __shared__ float se[32 * DD];
    int g = blockIdx.y;
    int tx = threadIdx.x, ty = threadIdx.y;
    int tid = ty * 64 + tx;
    int row0 = blockIdx.x * 32;
    for (int i = tid; i < 32 * DD; i += 256) {
        int r = i >> 6, c = i & 63;
        int gr = row0 + r;
        se[i] = (gr < n_rows) ? in[(ll)gr * DD + c] : 0.f;
    }
    for (int i = tid; i < DD * DD; i += 256) sW[i] = W[(ll)g * DD * DD + i];
    __syncthreads();

    float* outs[4] = {o0, o1, o2, o3};
    __half* houts[4] = {h0, h1, h2, h3};
    float* og = outs[g];
    __half* hg = houts[g];

    float bg = B[g * DD + tx];
    float acc[8] = {0, 0, 0, 0, 0, 0, 0, 0};
#pragma unroll
    for (int d4 = 0; d4 < DD; d4 += 4) {
        float w0 = sW[(d4 + 0) * DD + tx];
        float w1 = sW[(d4 + 1) * DD + tx];
        float w2 = sW[(d4 + 2) * DD + tx];
        float w3 = sW[(d4 + 3) * DD + tx];
#pragma unroll
        for (int rr = 0; rr < 8; ++rr) {
            float4 s4 = *(const float4*)(se + (ty + 4 * rr) * DD + d4);
            acc[rr] = fmaf(s4.x, w0, acc[rr]);
            acc[rr] = fmaf(s4.y, w1, acc[rr]);
            acc[rr] = fmaf(s4.z, w2, acc[rr]);
            acc[rr] = fmaf(s4.w, w3, acc[rr]);
        }
    }
#pragma unroll
    for (int rr = 0; rr < 8; ++rr) {
        int r = ty + 4 * rr;
        int gr = row0 + r;
        if (gr < n_rows) {
            float z = acc[rr] + bg;
            float sig = 1.f / (1.f + __expf(-z));
            float ov = se[r * DD + tx] * sig;
            ll idx = (ll)gr * DD + tx;
            if (og) og[idx] = ov;
            if (hg) hg[idx] = __float2half(ov);
        }
    }
}

// ---------------------------------------------------------------------------
static inline int blocks_for(ll threads, int bs) { return (int)((threads + bs - 1) / bs); }

extern "C" void kernel_launch(void* const* d_in, const int* in_sizes, int n_in,
                              void* d_out, int out_size) {
    const float* user_emb  = (const float*)d_in[0];
    const float* item_emb  = (const float*)d_in[1];
    const float* gating_w  = (const float*)d_in[2];
    const float* gating_b  = (const float*)d_in[3];
    const float* sgating_w = (const float*)d_in[4];
    const float* sgating_b = (const float*)d_in[5];
    const float* att_mat   = (const float*)d_in[6];
    const float* att_agg   = (const float*)d_in[7];
    const int*   hs_row = (const int*)d_in[8];
    const int*   hs_col = (const int*)d_in[9];
    const float* hs_val = (const float*)d_in[10];
    const int*   hj_row = (const int*)d_in[11];
    const int*   hj_col = (const int*)d_in[12];
    const float* hj_val = (const float*)d_in[13];
    const int*   hp_row = (const int*)d_in[14];
    const int*   hp_col = (const int*)d_in[15];
    const float* hp_val = (const float*)d_in[16];
    const int*   inter_row = (const int*)d_in[17];
    const int*   inter_col = (const int*)d_in[18];
    const float* inter_val = (const float*)d_in[19];

    const int NNZ_H = in_sizes[8];
    const int NNZ_I = in_sizes[17];

    float* out = (float*)d_out;
    const ll O_ITEM = S;
    const ll O_SG0 = S + SI;
    const ll O_SG1 = 2 * S + SI;
    const ll O_SG2 = 3 * S + SI;

    float*  gb; cudaGetSymbolAddress((void**)&gb, g_buf);
    __half* gh; cudaGetSymbolAddress((void**)&gh, g_h);
    int*   off; cudaGetSymbolAddress((void**)&off, g_off);
    int*   cnt; cudaGetSymbolAddress((void**)&cnt, g_cnt);
    short* rk;  cudaGetSymbolAddress((void**)&rk, g_rank);
    int2*  pr;  cudaGetSymbolAddress((void**)&pr, g_pair);

    static cudaStream_t sB = nullptr;
    static cudaEvent_t evRoot = nullptr, evB = nullptr;
    if (sB == nullptr) {
        cudaStreamCreateWithFlags(&sB, cudaStreamNonBlocking);
        cudaEventCreateWithFlags(&evRoot, cudaEventDisableTiming);
        cudaEventCreateWithFlags(&evB, cudaEventDisableTiming);
    }

    const int BS = 256;

    Build5 B;
    B.row[0] = hs_row;    B.col[0] = hs_col;    B.val[0] = hs_val;    B.nnz[0] = NNZ_H;
    B.row[1] = hj_row;    B.col[1] = hj_col;    B.val[1] = hj_val;    B.nnz[1] = NNZ_H;
    B.row[2] = hp_row;    B.col[2] = hp_col;    B.val[2] = hp_val;    B.nnz[2] = NNZ_H;
    B.row[3] = inter_row; B.col[3] = inter_col; B.val[3] = inter_val; B.nnz[3] = NNZ_I;
    B.row[4] = inter_col; B.col[4] = inter_row; B.val[4] = inter_val; B.nnz[4] = NNZ_I;
    ll po = 0, ro = 0;
    for (int m = 0; m < 5; ++m) {
        B.cnt[m] = cnt + m * (NU + 1);
        B.off[m] = off + m * (NU + 1);
        B.pair[m] = pr + po;  po += B.nnz[m];
        B.rank[m] = rk + ro;  ro += B.nnz[m];
    }

    // fork: build branch runs on sB concurrently with the dense prologue
    cudaEventRecord(evRoot, 0);
    cudaStreamWaitEvent(sB, evRoot, 0);

    // ---- branch B (side stream): CSR build ----
    int bpr = blocks_for((NNZ_H + 7) / 8, BS);
    zero_int_kernel<<<blocks_for(OFFLEN, BS), BS, 0, sB>>>(cnt, OFFLEN);
    hist5_kernel<<<5 * bpr, BS, 0, sB>>>(B, bpr);
    scan_kernel<<<5, 1024, 0, sB>>>();
    scat5_kernel<<<5 * bpr, BS, 0, sB>>>(B, bpr);
    cudaEventRecord(evB, sB);

    // ---- branch A (default stream): dense prologue ----
    compute_v_kernel<<<1, 64>>>(att_mat, att_agg);
    item_h_kernel<<<blocks_for(SI / 2, BS), BS>>>(item_emb, gh + XIT, (int)(SI / 2));
    cudaMemcpyAsync(out + O_ITEM, item_emb, SI * sizeof(float), cudaMemcpyDeviceToDevice, 0);

    dim3 gdim(64, 4);
    dim3 ggrid4((NU + 31) / 32, 4);
    gating_kernel<<<ggrid4, gdim>>>(user_emb, gating_w, gating_b, NU,
                                    gb + ACC0, gb + ACC1, gb + ACC2, gb + ACCS,
                                    gh + XG0, gh + XG1, gh + XG2, gh + XGS);

    const int uwb = blocks_for((ll)NU * 32, BS);
    attn_h_kernel<<<uwb, BS>>>(gh + XG0, gh + XG1, gh + XG2, gh + XGS, gb + VOFF,
                               gh + XMIX, NU);

    // join: SpMM needs both branches
    cudaStreamWaitEvent(0, evB, 0);

    const ll TOTW = 4ll * NU + NI;
    const int swb = blocks_for(TOTW * 32, BS);

    // ---- layer 1 ----
    Spmm5 A1;
    A1.off[0] = B.off[0]; A1.pair[0] = B.pair[0]; A1.x[0] = gh + XG0; A1.y[0] = gh + XT0; A1.acc[0] = gb + ACC0;
    A1.off[1] = B.off[1]; A1.pair[1] = B.pair[1]; A1.x[1] = gh + XG1; A1.y[1] = gh + XT1; A1.acc[1] = gb + ACC1;
    A1.off[2] = B.off[2]; A1.pair[2] = B.pair[2]; A1.x[2] = gh + XG2; A1.y[2] = gh + XT2; A1.acc[2] = gb + ACC2;
    A1.off[3] = B.off[4]; A1.pair[3] = B.pair[4]; A1.x[3] = gh + XMIX; A1.y[3] = gh + XITA; A1.acc[3] = out + O_ITEM;
    A1.off[4] = B.off[3]; A1.pair[4] = B.pair[3]; A1.x[4] = gh + XIT; A1.y[4] = gh + XUS; A1.acc[4] = gb + ACCS;
    spmm5_kernel<<<swb, BS>>>(A1);

    // ---- layer 2 ----
    attn_h_kernel<<<uwb, BS>>>(gh + XT0, gh + XT1, gh + XT2, gh + XUS, gb + VOFF,
                               gh + XMIX, NU);
    Spmm5 A2;
    A2.off[0] = B.off[0]; A2.pair[0] = B.pair[0]; A2.x[0] = gh + XT0; A2.y[0] = nullptr; A2.acc[0] = gb + ACC0;
    A2.off[1] = B.off[1]; A2.pair[1] = B.pair[1]; A2.x[1] = gh + XT1; A2.y[1] = nullptr; A2.acc[1] = gb + ACC1;
    A2.off[2] = B.off[2]; A2.pair[2] = B.pair[2]; A2.x[2] = gh + XT2; A2.y[2] = nullptr; A2.acc[2] = gb + ACC2;
    A2.off[3] = B.off[4]; A2.pair[3] = B.pair[4]; A2.x[3] = gh + XMIX; A2.y[3] = nullptr; A2.acc[3] = out + O_ITEM;
    A2.off[4] = B.off[3]; A2.pair[4] = B.pair[3]; A2.x[4] = gh + XITA; A2.y[4] = nullptr; A2.acc[4] = gb + ACCS;
    spmm5_kernel<<<swb, BS>>>(A2);

    // ---- final ----
    attn_f_kernel<<<uwb, BS>>>(gb + ACC0, gb + ACC1, gb + ACC2, gb + ACCS, gb + VOFF,
                               out, NU);
    dim3 ggrid3((NU + 31) / 32, 3);
    gating_kernel<<<ggrid3, gdim>>>(out, sgating_w, sgating_b, NU,
                                    out + O_SG0, out + O_SG1, out + O_SG2, nullptr,
                                    nullptr, nullptr, nullptr, nullptr);
}